// round 13
// baseline (speedup 1.0000x reference)
#include <cuda_runtime.h>
#include <cuda_fp16.h>
#include <cstdint>

#define BN   16
#define CH   128
#define HWN  1024
#define SN   8
#define SBN  128
#define CHW  131072

#define GUARD   64
#define RPI     1344
#define TOTROWS   (GUARD + 128*RPI + 256)
#define TOTROWS_S (GUARD + 16*RPI + 256)

// mmaconv smem (bytes): X window 200 rows x 256B, then two 16KB A chunk buffers
#define AB_OFF 51200
#define DSMEM_TOTAL 83968

// stats slots (2 floats per img): K=0, V=256, HT=512, Q=544, ATT=576, O=608
#define ST_K   0
#define ST_V   256
#define ST_HT  512
#define ST_Q   544
#define ST_ATT 576
#define ST_O   608

__device__ float g_ht [BN*CHW];
__device__ float g_q  [BN*CHW];
__device__ float g_k  [SBN*CHW];
__device__ float g_v  [SBN*CHW];
__device__ float g_att[BN*CHW];
__device__ float g_o  [BN*CHW];
__device__ float g_stats[640];
__device__ float g_pool[SBN*2*HWN];
__device__ float g_qsa[BN*HWN];
__device__ float g_ksa[SBN*HWN];
__device__ float g_sprob[SBN*HWN];
__device__ float g_tl[SN*BN];
__device__ float g_tp[SN*BN];
__device__ float g_peN[SN*2*CH];
__device__ float g_se3[BN*CH];
__device__ float g_Pb[SN*CH*9];
__device__ __half g_nhwc [(size_t)TOTROWS*256];
__device__ __half g_nhwcS[(size_t)TOTROWS_S*256];
// wrep single-split: kpre(294912)|vpre(294912)|qpre(147456)|outt(294912)|enc(147456)|vpost(16384)
__device__ __half g_wrep[1196032];

__device__ __forceinline__ float sigmf(float x){ return 1.f/(1.f + __expf(-x)); }
__device__ __forceinline__ bool mask_at(const unsigned char* m, int b){
    if (m[1] != 0) return m[b] != 0;
    const unsigned int* w = (const unsigned int*)m;
    return w[b] != 0;
}

__device__ __forceinline__ uint32_t smem_u32(const void* p){
    uint32_t a;
    asm("{ .reg .u64 t; cvta.to.shared.u64 t, %1; cvt.u32.u64 %0, t; }" : "=r"(a) : "l"(p));
    return a;
}
__device__ __forceinline__ void mma16816(float* d, uint32_t a0, uint32_t a1, uint32_t a2,
                                         uint32_t a3, uint32_t b0, uint32_t b1){
    asm volatile("mma.sync.aligned.m16n8k16.row.col.f32.f16.f16.f32 "
        "{%0,%1,%2,%3}, {%4,%5,%6,%7}, {%8,%9}, {%0,%1,%2,%3};"
        : "+f"(d[0]),"+f"(d[1]),"+f"(d[2]),"+f"(d[3])
        : "r"(a0),"r"(a1),"r"(a2),"r"(a3),"r"(b0),"r"(b1));
}
__device__ __forceinline__ void ldsm4(uint32_t& r0,uint32_t& r1,uint32_t& r2,uint32_t& r3,
                                      uint32_t addr){
    asm volatile("ldmatrix.sync.aligned.m8n8.x4.shared.b16 {%0,%1,%2,%3}, [%4];"
        : "=r"(r0),"=r"(r1),"=r"(r2),"=r"(r3) : "r"(addr));
}
__device__ __forceinline__ void cpa16(uint32_t d, const void* s){
    asm volatile("cp.async.cg.shared.global [%0], [%1], 16;" :: "r"(d), "l"(s));
}
__device__ __forceinline__ void cp_commit(){ asm volatile("cp.async.commit_group;" ::: "memory"); }
__device__ __forceinline__ void cp_wait0(){ asm volatile("cp.async.wait_group 0;" ::: "memory"); }

// ---- misc ----
__global__ void zero_stats_k(){ if (threadIdx.x < 640) g_stats[threadIdx.x] = 0.f; }

__global__ void pe_norm_k(const float* __restrict__ pe, float* __restrict__ peN)
{
    int s = blockIdx.x, t = threadIdx.x;
    float v = pe[s*256 + t];
    float q = v*v;
    #pragma unroll
    for (int o=16;o;o>>=1) q += __shfl_down_sync(0xffffffffu, q, o);
    __shared__ float a[8];
    __shared__ float fac;
    if ((t&31)==0) a[t>>5] = q;
    __syncthreads();
    if (t==0){
        float S=0.f;
        #pragma unroll
        for (int i=0;i<8;i++) S += a[i];
        float n = sqrtf(S);
        fac = fminf(1.f, 1.f/fmaxf(n, 1e-7f));
    }
    __syncthreads();
    peN[s*256 + t] = v*fac;
}

// big buffer fill: kv concat (128 imgs, 256 ch)
__global__ void fill_nhwc_k(const float* __restrict__ hid, const float* __restrict__ oq)
{
    __shared__ float s[32][257];
    int t = threadIdx.x;
    int img = blockIdx.x>>5, y = blockIdx.x&31;
    int xg = t&31, cg = t>>5;
    size_t rb = GUARD + (size_t)img*RPI + (size_t)(y+1)*34;
    #pragma unroll
    for (int cc=0; cc<32; cc++){
        int c = cc*8 + cg;
        const float* src = (c<128) ? hid + ((size_t)img*128 + c)*1024
                                   : oq  + ((size_t)img*128 + (c-128))*1024;
        s[xg][c] = src[y*32 + xg];
    }
    __syncthreads();
    #pragma unroll
    for (int xs=0; xs<32; xs++)
        g_nhwc[(rb + xs + 1)*256 + t] = __float2half(s[xs][t]);
}

// small buffer fill: inputs (ch0-63)
__global__ void fill_in_k(const float* __restrict__ inputs)
{
    __shared__ float s[32][65];
    int t = threadIdx.x;
    int img = blockIdx.x>>5, y = blockIdx.x&31;
    int xg = t&31, cg = t>>5;
    size_t rb = GUARD + (size_t)img*RPI + (size_t)(y+1)*34;
    #pragma unroll
    for (int cc=0; cc<8; cc++){
        int c = cc*8 + cg;
        s[xg][c] = inputs[((size_t)img*64 + c)*1024 + y*32 + xg];
    }
    __syncthreads();
    if (t < 64){
        #pragma unroll
        for (int xs=0; xs<32; xs++)
            g_nhwcS[(rb + xs + 1)*256 + t] = __float2half(s[xs][t]);
    }
}

// gn(ht)+silu applied in place AND written as fp16 NHWC (ch0-127)
__global__ void gn_ht_fill_k(const float* __restrict__ gw, const float* __restrict__ gb)
{
    __shared__ float sm[32][129];
    __shared__ float sc[128], sh[128];
    int t = threadIdx.x;
    int img = blockIdx.x>>5, y = blockIdx.x&31;
    int xg = t&31, cg = t>>5;
    if (t < 128){
        float sum = g_stats[ST_HT+2*img], ssq = g_stats[ST_HT+2*img+1];
        float mu = sum*(1.f/131072.f);
        float rs = rsqrtf(ssq*(1.f/131072.f) - mu*mu + 1e-5f);
        float s_ = rs*gw[t];
        sc[t] = s_; sh[t] = gb[t] - mu*s_;
    }
    __syncthreads();
    int p = y*32 + xg;
    #pragma unroll
    for (int cc=0; cc<16; cc++){
        int c = cc*8 + cg;
        float v = g_ht[((size_t)img*128 + c)*1024 + p];
        v = v*sc[c] + sh[c];
        v *= sigmf(v);
        g_ht[((size_t)img*128 + c)*1024 + p] = v;
        sm[xg][c] = v;
    }
    __syncthreads();
    size_t rb = GUARD + (size_t)img*RPI + (size_t)(y+1)*34;
    if (t < 128){
        #pragma unroll
        for (int xs=0; xs<32; xs++)
            g_nhwcS[(rb + xs + 1)*256 + t] = __float2half(sm[xs][t]);
    }
}

// small buffer fill: concat(inputs[64], att+ht[128]) -> ch0-191
__global__ void xcat_fill_k(const float* __restrict__ inputs)
{
    __shared__ float s[32][193];
    int t = threadIdx.x;
    int img = blockIdx.x>>5, y = blockIdx.x&31;
    int xg = t&31, cg = t>>5;
    size_t rb = GUARD + (size_t)img*RPI + (size_t)(y+1)*34;
    #pragma unroll
    for (int cc=0; cc<24; cc++){
        int c = cc*8 + cg;
        float val;
        if (c < 64) val = inputs[((size_t)img*64 + c)*1024 + y*32 + xg];
        else {
            int c2 = c - 64;
            val = g_att[((size_t)img*128 + c2)*1024 + y*32 + xg]
                + g_ht [((size_t)img*128 + c2)*1024 + y*32 + xg];
        }
        s[xg][c] = val;
    }
    __syncthreads();
    if (t < 192){
        #pragma unroll
        for (int xs=0; xs<32; xs++)
            g_nhwcS[(rb + xs + 1)*256 + t] = __float2half(s[xs][t]);
    }
}

// ---- weight repack: [tap*nkc+kc][co][128k] fp16 single split; zero-pad cin ----
__global__ void wrep_k(const float* __restrict__ w, __half* __restrict__ dst,
                       int cin, int nkc)
{
    int n = nkc*147456;
    int i = blockIdx.x*blockDim.x + threadIdx.x;
    if (i >= n) return;
    int kl = i & 127;
    int r = i >> 7;
    int co = r & 127; r >>= 7;
    int kc = r % nkc;
    int tap = r / nkc;
    int cin_idx = kc*128 + kl;
    float val = (cin_idx < cin) ? w[((size_t)co*cin + cin_idx)*9 + tap] : 0.f;
    dst[((tap*nkc+kc)*128 + co)*128 + kl] = __float2half(val);
}

__global__ void wrep1x1_k(const float* __restrict__ w, __half* __restrict__ dst)
{
    int i = blockIdx.x*blockDim.x + threadIdx.x;
    if (i < 16384) dst[i] = __float2half(w[i]);
}

// ---- pe correction with border masks ----
__global__ void pbconv_k(const float* __restrict__ w)
{
    int s = blockIdx.x, co = threadIdx.x;
    float P[9];
    #pragma unroll
    for (int tap=0;tap<9;tap++){
        float acc = 0.f;
        for (int c=0;c<256;c++)
            acc += g_peN[s*256 + c] * w[((size_t)co*256 + c)*9 + tap];
        P[tap] = acc;
    }
    #pragma unroll
    for (int yc=0;yc<3;yc++){
        #pragma unroll
        for (int xc=0;xc<3;xc++){
            float tot = 0.f;
            #pragma unroll
            for (int dy=0;dy<3;dy++){
                if ((yc==0 && dy==0) || (yc==2 && dy==2)) continue;
                float rs = P[dy*3+1];
                if (xc!=0) rs += P[dy*3+0];
                if (xc!=2) rs += P[dy*3+2];
                tot += rs;
            }
            g_Pb[(s*128+co)*9 + yc*3+xc] = tot;
        }
    }
}

// ---- stage one 16KB A chunk (128co x 64k) ----
__device__ __forceinline__ void stage_chunk(uint32_t ab, const __half* wrep,
                                            int slot, int kh, int t)
{
    const char* asrc = (const char*)(wrep + (size_t)slot*16384 + kh*64);
    #pragma unroll
    for (int j=0;j<4;j++){
        int i = j*256 + t;
        uint32_t r = (uint32_t)(i>>3), sg = (uint32_t)(i&7);
        cpa16(ab + r*128 + ((sg^(r&7))<<4), asrc + (size_t)r*256 + sg*16);
    }
}

// ---- conv on one chunk: 64-k slice ----
__device__ __forceinline__ void conv_chunk(uint32_t xb, uint32_t ab, int tap, int kh,
                                           int lane, int cob, int pxb,
                                           float acc[4][4][4])
{
    const int lr  = lane & 7;
    const int hsA = lane >> 4;
    const int hsB = (lane >> 3) & 1;
    const int dy = tap/3, dx = tap - dy*3;
    const int dlt = (dy-1)*34 + (dx-1);

    uint32_t rowA[4], rsA[4];
    #pragma unroll
    for (int mi=0;mi<4;mi++){
        int r = cob + mi*16 + lr + ((lane>>3)&1)*8;
        rowA[mi] = (uint32_t)r*128u; rsA[mi] = (uint32_t)(r&7);
    }
    uint32_t rowB[2], rsB[2];
    #pragma unroll
    for (int nn=0;nn<2;nn++){
        int r = 36 + dlt + pxb + nn*16 + lr + (lane>>4)*8;
        rowB[nn] = (uint32_t)r*256u; rsB[nn] = (uint32_t)(r&7);
    }
    #pragma unroll
    for (int k8=0;k8<4;k8++){
        uint32_t a[4][4];
        #pragma unroll
        for (int mi=0;mi<4;mi++){
            uint32_t sgi = (uint32_t)(k8*2 + hsA);
            ldsm4(a[mi][0],a[mi][1],a[mi][2],a[mi][3],
                  ab + rowA[mi] + ((sgi ^ rsA[mi])<<4));
        }
        #pragma unroll
        for (int nn=0;nn<2;nn++){
            uint32_t sgi = (uint32_t)((kh*4+k8)*2 + hsB);
            uint32_t b0,b1,b2,b3;
            ldsm4(b0,b1,b2,b3, xb + rowB[nn] + ((sgi ^ rsB[nn])<<4));
            #pragma unroll
            for (int mi=0;mi<4;mi++){
                mma16816(acc[mi][2*nn],   a[mi][0],a[mi][1],a[mi][2],a[mi][3], b0,b1);
                mma16816(acc[mi][2*nn+1], a[mi][0],a[mi][1],a[mi][2],a[mi][3], b2,b3);
            }
        }
    }
}

// ---- mma.sync fp16 implicit conv, double-buffered A chunks, fused GN sums ----
__global__ __launch_bounds__(256,2)
void mmaconv_k(const __half* __restrict__ wrep,
               const __half* __restrict__ nhwc,
               const float* __restrict__ Pb,
               float* __restrict__ dst,
               float* __restrict__ stats, int nkc, int t0, int t1)
{
    extern __shared__ char dsm[];
    const uint32_t sb = smem_u32(dsm);
    const uint32_t XB = sb;
    const uint32_t AB = sb + AB_OFF;
    const int t = threadIdx.x;
    const int wid = t>>5, lane = t&31;
    const int img = blockIdx.x/10;
    const int p0  = (blockIdx.x%10)*128;
    const int s   = img>>4;
    const int cob = (wid&1)*64;
    const int pxb = (wid>>1)*32;
    const int nch = 2*(t1-t0);

    float acc[4][4][4];
    #pragma unroll
    for (int mi=0;mi<4;mi++)
    #pragma unroll
    for (int ni=0;ni<4;ni++)
    #pragma unroll
    for (int e=0;e<4;e++) acc[mi][ni][e]=0.f;

    for (int kc=0; kc<nkc; kc++){
        // stage X window: 200 rows x 128k fp16 (one kc half)
        {
            const char* src = (const char*)nhwc
                + ((size_t)GUARD + (size_t)img*RPI + p0 - 36)*512 + kc*256;
            #pragma unroll
            for (int j=0;j<13;j++){
                int i = j*256 + t;
                if (i < 3200){
                    uint32_t r = (uint32_t)(i>>4), sg = (uint32_t)(i&15);
                    cpa16(XB + r*256 + ((sg^(r&7))<<4), src + (size_t)r*512 + sg*16);
                }
            }
            cp_commit();
        }
        stage_chunk(AB, wrep, t0*nkc + kc, 0, t);
        cp_commit();
        cp_wait0(); __syncthreads();
        for (int idx=0; idx<nch; idx++){
            uint32_t cur = AB + (uint32_t)(idx&1)*16384u;
            if (idx+1 < nch){
                int nidx = idx+1;
                stage_chunk(AB + (uint32_t)(nidx&1)*16384u, wrep,
                            (t0 + (nidx>>1))*nkc + kc, nidx&1, t);
                cp_commit();
            }
            conv_chunk(XB, cur, t0 + (idx>>1), idx&1, lane, cob, pxb, acc);
            if (idx+1 < nch) cp_wait0();
            __syncthreads();
        }
    }

    // epilogue: stores + local GN partial sums
    const int g  = lane>>2;
    const int t2 = (lane&3)*2;
    float sm_=0.f, sq_=0.f;
    #pragma unroll
    for (int mi=0;mi<4;mi++){
        #pragma unroll
        for (int n8=0;n8<4;n8++){
            #pragma unroll
            for (int e=0;e<4;e++){
                int co  = cob + mi*16 + g + ((e>>1)<<3);
                int col = pxb + n8*8 + t2 + (e&1);
                int pp  = p0 + col;
                int q34 = pp/34;
                int yy  = q34 - 1;
                int xx  = pp - q34*34 - 1;
                if ((unsigned)yy < 32u && (unsigned)xx < 32u){
                    float v = acc[mi][n8][e];
                    if (Pb){
                        int yc = (yy==0)?0:((yy==31)?2:1);
                        int xc = (xx==0)?0:((xx==31)?2:1);
                        v += Pb[(s*128+co)*9 + yc*3+xc];
                    }
                    dst[((size_t)img*128+co)*1024 + (yy<<5)+xx] = v;
                    sm_ += v; sq_ += v*v;
                }
            }
        }
    }
    #pragma unroll
    for (int o=16;o;o>>=1){
        sm_ += __shfl_down_sync(0xffffffffu, sm_, o);
        sq_ += __shfl_down_sync(0xffffffffu, sq_, o);
    }
    float* red = (float*)dsm;
    __syncthreads();
    if (lane==0){ red[wid*2] = sm_; red[wid*2+1] = sq_; }
    __syncthreads();
    if (t==0){
        float S=0.f, S2=0.f;
        #pragma unroll
        for (int w=0;w<8;w++){ S += red[w*2]; S2 += red[w*2+1]; }
        atomicAdd(&stats[img*2],   S);
        atomicAdd(&stats[img*2+1], S2);
    }
}

// ---- GN apply from raw sums (o) ----
__global__ void gn_apply_k(float* __restrict__ x, const float* __restrict__ stats,
                           const float* __restrict__ gw, const float* __restrict__ gb,
                           int nimg, int act)
{
    int n4 = nimg*32768;
    for (int i = blockIdx.x*blockDim.x + threadIdx.x; i < n4; i += gridDim.x*blockDim.x){
        int base = i<<2;
        int img = base>>17; int c = (base>>10)&127;
        float sum = stats[2*img], ssq = stats[2*img+1];
        float mu = sum*(1.f/131072.f);
        float rs = rsqrtf(ssq*(1.f/131072.f) - mu*mu + 1e-5f);
        float sc = rs*gw[c];
        float sh = gb[c] - mu*sc;
        float4 v = ((float4*)x)[i];
        v.x = v.x*sc+sh; v.y = v.y*sc+sh; v.z = v.z*sc+sh; v.w = v.w*sc+sh;
        if (act){
            v.x *= sigmf(v.x); v.y *= sigmf(v.y); v.z *= sigmf(v.z); v.w *= sigmf(v.w);
        }
        ((float4*)x)[i] = v;
    }
}

// ---- GN apply + channel mean/max pool fused (k, q) ----
__global__ void gn_apply_pool_k(float* __restrict__ x, const float* __restrict__ stats,
                                const float* __restrict__ gw, const float* __restrict__ gb,
                                float* __restrict__ pool)
{
    __shared__ float sc[128], sh[128];
    int t = threadIdx.x;
    int img = blockIdx.x>>2;
    int p = ((blockIdx.x&3)<<8) + t;
    if (t < 128){
        float sum = stats[2*img], ssq = stats[2*img+1];
        float mu = sum*(1.f/131072.f);
        float rs = rsqrtf(ssq*(1.f/131072.f) - mu*mu + 1e-5f);
        float scv = rs*gw[t];
        sc[t] = scv; sh[t] = gb[t] - mu*scv;
    }
    __syncthreads();
    float* base = x + (size_t)img*CHW + p;
    float s = 0.f, m = -3.402823466e38f;
    #pragma unroll 4
    for (int c=0;c<128;c++){
        float y = base[(size_t)c<<10]*sc[c] + sh[c];
        base[(size_t)c<<10] = y;
        s += y; m = fmaxf(m, y);
    }
    pool[img*2048 + p]        = s*(1.f/128.f);
    pool[img*2048 + 1024 + p] = m;
}

// ---- GN apply att (silu) + newout write fused ----
__global__ void gn_apply_att_k(float* __restrict__ x, const float* __restrict__ stats,
                               const float* __restrict__ gw, const float* __restrict__ gb,
                               const unsigned char* __restrict__ mask,
                               float* __restrict__ out)
{
    int i = blockIdx.x*blockDim.x + threadIdx.x;
    if (i >= BN*32768) return;
    int base = i<<2;
    int img = base>>17; int c = (base>>10)&127;
    float sum = stats[2*img], ssq = stats[2*img+1];
    float mu = sum*(1.f/131072.f);
    float rs = rsqrtf(ssq*(1.f/131072.f) - mu*mu + 1e-5f);
    float sc = rs*gw[c];
    float sh = gb[c] - mu*sc;
    float4 v = ((float4*)x)[i];
    v.x = v.x*sc+sh; v.y = v.y*sc+sh; v.z = v.z*sc+sh; v.w = v.w*sc+sh;
    v.x *= sigmf(v.x); v.y *= sigmf(v.y); v.z *= sigmf(v.z); v.w *= sigmf(v.w);
    ((float4*)x)[i] = v;
    float4 z = mask_at(mask, img) ? v : make_float4(0.f,0.f,0.f,0.f);
    *(float4*)&out[(size_t)2*BN*CHW + base] = z;
}

// ---- 2->1 3x3 conv + sigmoid ----
__global__ void saconv_k(const float* __restrict__ pool, const float* __restrict__ w,
                         const float* __restrict__ b, float* __restrict__ sa, int nimg)
{
    int i = blockIdx.x*blockDim.x + threadIdx.x;
    if (i >= nimg*HWN) return;
    int img = i>>10, p = i&1023, y = p>>5, x = p&31;
    float acc = b[0];
    #pragma unroll
    for (int c2=0;c2<2;c2++)
    #pragma unroll
    for (int dy=-1;dy<=1;dy++)
    #pragma unroll
    for (int dx=-1;dx<=1;dx++){
        int yy=y+dy, xx=x+dx;
        if ((unsigned)yy<32u && (unsigned)xx<32u)
            acc += pool[img*2048 + c2*1024 + (yy<<5)+xx] * w[c2*9 + (dy+1)*3 + (dx+1)];
    }
    sa[i] = sigmf(acc);
}

// ---- fused attention: qfg -> sprob + tlogit, one block per (s,b) image ----
__global__ void attn_k()
{
    __shared__ float fq[128];
    __shared__ float red[8];
    int img = blockIdx.x, b = img & 15;
    int t = threadIdx.x, wid = t>>5, lane = t&31;

    // phase 1: qfg[c] = mean_p( q[b,c,p] * ksa[img,p] )
    const float* kap = g_ksa + (size_t)img*1024;
    for (int c = wid; c < 128; c += 8){
        const float* qp = g_q + ((size_t)b*128 + c)*1024;
        float acc = 0.f;
        for (int p=lane; p<1024; p+=32) acc += qp[p]*kap[p];
        #pragma unroll
        for (int o=16;o;o>>=1) acc += __shfl_down_sync(0xffffffffu, acc, o);
        if (!lane) fq[c] = acc*(1.f/1024.f);
    }
    __syncthreads();

    // phase 2: sprob[p] and t-logit partial in one pass over k[img]
    float tl = 0.f;
    for (int p=t; p<1024; p+=256){
        const float* kp = g_k + (size_t)img*CHW + p;
        const float* qp = g_q + (size_t)b*CHW + p;
        float a1 = 0.f, a2 = 0.f;
        #pragma unroll 4
        for (int c=0;c<128;c++){
            float kv = kp[(size_t)c<<10];
            a1 += fq[c]*kv;
            a2 += qp[(size_t)c<<10]*kv;
        }
        g_sprob[img*1024 + p] = sigmf(a1);
        tl += a2 * g_qsa[b*1024+p] * kap[p];
    }
    #pragma unroll
    for (int o=16;o;o>>=1) tl += __shfl_down_sync(0xffffffffu, tl, o);
    if (!lane) red[wid] = tl;
    __syncthreads();
    if (t==0){
        float S=0.f;
        #pragma unroll
        for (int i=0;i<8;i++) S += red[i];
        g_tl[img] = S * rsqrtf(131072.f);
    }
}

__global__ void tprob_k()
{
    int b = threadIdx.x;
    if (b >= 16) return;
    float m = -3.402823466e38f;
    #pragma unroll
    for (int s=0;s<8;s++) m = fmaxf(m, g_tl[s*16+b]);
    float e[8]; float sum = 0.f;
    #pragma unroll
    for (int s=0;s<8;s++){ e[s] = __expf(g_tl[s*16+b] - m); sum += e[s]; }
    float inv = 1.f/sum;
    #pragma unroll
    for (int s=0;s<8;s++) g_tp[s*16+b] = e[s]*inv;
}

// ---- av with fused v-GN, writes fp16 NHWC directly ----
__global__ void av_fill_k(const float* __restrict__ vgw, const float* __restrict__ vgb)
{
    __shared__ float sm[32][129];
    __shared__ float sc[8][128], sh[8][128];
    int t = threadIdx.x;
    int img = blockIdx.x>>5, y = blockIdx.x&31;
    int xg = t&31, cg = t>>5;
    if (t < 128){
        #pragma unroll
        for (int s=0;s<8;s++){
            int i2 = s*16 + img;
            float sum = g_stats[ST_V+2*i2], ssq = g_stats[ST_V+2*i2+1];
            float mu = sum*(1.f/131072.f);
            float rs = rsqrtf(ssq*(1.f/131072.f) - mu*mu + 1e-5f);
            float s_ = rs*vgw[t];
            sc[s][t] = s_; sh[s][t] = vgb[t] - mu*s_;
        }
    }
    __syncthreads();
    int p = y*32 + xg;
    float ws[8];
    #pragma unroll
    for (int s=0;s<8;s++){
        int i2 = s*16 + img;
        ws[s] = g_tp[i2]*g_sprob[i2*1024 + p];
    }
    #pragma unroll
    for (int cc=0; cc<16; cc++){
        int c = cc*8 + cg;
        float acc = 0.f;
        #pragma unroll
        for (int s=0;s<8;s++){
            int i2 = s*16 + img;
            float vv = g_v[((size_t)i2*128 + c)*1024 + p];
            acc += ws[s]*(vv*sc[s][c] + sh[s][c]);
        }
        sm[xg][c] = acc;
    }
    __syncthreads();
    size_t rb = GUARD + (size_t)img*RPI + (size_t)(y+1)*34;
    if (t < 128){
        #pragma unroll
        for (int xs=0; xs<32; xs++)
            g_nhwcS[(rb + xs + 1)*256 + t] = __float2half(sm[xs][t]);
    }
}

// ---- fused SE ----
__global__ void se_k(const float* __restrict__ w1, const float* __restrict__ b1,
                     const float* __restrict__ w2, const float* __restrict__ b2)
{
    __shared__ float mean[128], f1[32];
    int b = blockIdx.x;
    int w = threadIdx.x>>5, lane = threadIdx.x&31;
    for (int c=w; c<128; c+=8){
        const float* p = g_o + ((size_t)b*128 + c)*1024;
        float s = 0.f;
        for (int i=lane; i<1024; i+=32) s += p[i];
        #pragma unroll
        for (int o=16;o;o>>=1) s += __shfl_down_sync(0xffffffffu, s, o);
        if (!lane) mean[c] = s*(1.f/1024.f);
    }
    __syncthreads();
    if (threadIdx.x < 32){
        int j = threadIdx.x;
        float acc = b1[j];
        #pragma unroll 4
        for (int c=0;c<128;c++) acc += mean[c]*w1[j*128+c];
        f1[j] = fmaxf(acc, 0.f);
    }
    __syncthreads();
    if (threadIdx.x < 128){
        int c = threadIdx.x;
        float acc = b2[c];
        #pragma unroll
        for (int j=0;j<32;j++) acc += f1[j]*w2[c*32+j];
        g_se3[b*128+c] = sigmf(acc);
    }
}

__global__ void final_k(float* __restrict__ out)
{
    int i = blockIdx.x*blockDim.x + threadIdx.x;
    if (i >= BN*CHW/4) return;
    int base = i<<2;
    int b = base>>17; int c = (base>>10)&127;
    float g = 1.f + g_se3[b*128+c];
    float4 o4 = *(const float4*)&g_o[base];
    o4.x*=g; o4.y*=g; o4.z*=g; o4.w*=g;
    *(float4*)&out[base] = o4;
    *(float4*)&out[(size_t)BN*CHW + base] = *(const float4*)&g_ht[base];
}

// ---- host launcher ----
extern "C" void kernel_launch(void* const* d_in, const int* in_sizes, int n_in,
                              void* d_out, int out_size)
{
    (void)in_sizes; (void)n_in; (void)out_size;
    const float* inputs  = (const float*)d_in[0];
    const float* hidden  = (const float*)d_in[1];
    const float* outq    = (const float*)d_in[2];
    const unsigned char* mask = (const unsigned char*)d_in[3];
    const float* enc_w   = (const float*)d_in[4];
    const float* enc_gw  = (const float*)d_in[5];
    const float* enc_gb  = (const float*)d_in[6];
    const float* qpre_w  = (const float*)d_in[7];
    const float* qpre_gw = (const float*)d_in[8];
    const float* qpre_gb = (const float*)d_in[9];
    const float* kpre_w  = (const float*)d_in[10];
    const float* kpre_gw = (const float*)d_in[11];
    const float* kpre_gb = (const float*)d_in[12];
    const float* vpre_w  = (const float*)d_in[13];
    const float* vpre_gw = (const float*)d_in[14];
    const float* vpre_gb = (const float*)d_in[15];
    const float* qsa_w   = (const float*)d_in[16];
    const float* qsa_b   = (const float*)d_in[17];
    const float* ksa_w   = (const float*)d_in[18];
    const float* ksa_b   = (const float*)d_in[19];
    const float* vpost_w = (const float*)d_in[20];
    const float* vpost_gw= (const float*)d_in[21];
    const float* vpost_gb= (const float*)d_in[22];
    const float* pos_emb = (const float*)d_in[23];
    const float* outt_w  = (const float*)d_in[24];
    const float* outt_gw = (const float*)d_in[25];
    const float* outt_gb = (const float*)d_in[26];
    const float* se_w1   = (const float*)d_in[27];
    const float* se_b1   = (const float*)d_in[28];
    const float* se_w2   = (const float*)d_in[29];
    const float* se_b2   = (const float*)d_in[30];
    float* out = (float*)d_out;

    float *ht,*q,*k,*v,*att,*o,*stats,*pool,*qsa,*ksa,*peN,*Pb;
    __half *wrep, *nhwc, *nhwcS;
    cudaGetSymbolAddress((void**)&ht,   g_ht);
    cudaGetSymbolAddress((void**)&q,    g_q);
    cudaGetSymbolAddress((void**)&k,    g_k);
    cudaGetSymbolAddress((void**)&v,    g_v);
    cudaGetSymbolAddress((void**)&att,  g_att);
    cudaGetSymbolAddress((void**)&o,    g_o);
    cudaGetSymbolAddress((void**)&stats,g_stats);
    cudaGetSymbolAddress((void**)&pool, g_pool);
    cudaGetSymbolAddress((void**)&qsa,  g_qsa);
    cudaGetSymbolAddress((void**)&ksa,  g_ksa);
    cudaGetSymbolAddress((void**)&peN,  g_peN);
    cudaGetSymbolAddress((void**)&Pb,   g_Pb);
    cudaGetSymbolAddress((void**)&wrep, g_wrep);
    cudaGetSymbolAddress((void**)&nhwc, g_nhwc);
    cudaGetSymbolAddress((void**)&nhwcS,g_nhwcS);

    const size_t WR_KPRE  = 0;
    const size_t WR_VPRE  = 294912;
    const size_t WR_QPRE  = 589824;
    const size_t WR_OUTT  = 737280;
    const size_t WR_ENC   = 1032192;
    const size_t WR_VPOST = 1179648;   // accessed as slot 4 via -4*16384 base

    cudaFuncSetAttribute(mmaconv_k, cudaFuncAttributeMaxDynamicSharedMemorySize, DSMEM_TOTAL);

    zero_stats_k<<<1,640>>>();
    fill_nhwc_k<<<4096,256>>>(hidden, outq);
    wrep_k<<<1152,256>>>(kpre_w, wrep + WR_KPRE, 256, 2);
    mmaconv_k<<<1280,256,DSMEM_TOTAL>>>(wrep + WR_KPRE, nhwc, nullptr, k, stats + ST_K, 2, 0, 9);
    wrep_k<<<1152,256>>>(vpre_w, wrep + WR_VPRE, 256, 2);
    pe_norm_k<<<8,256>>>(pos_emb, peN);
    pbconv_k<<<8,128>>>(vpre_w);
    mmaconv_k<<<1280,256,DSMEM_TOTAL>>>(wrep + WR_VPRE, nhwc, Pb, v, stats + ST_V, 2, 0, 9);

    fill_in_k<<<512,256>>>(inputs);
    wrep_k<<<576,256>>>(enc_w,  wrep + WR_ENC,  64, 1);
    wrep_k<<<576,256>>>(qpre_w, wrep + WR_QPRE, 128, 1);
    wrep_k<<<1152,256>>>(outt_w, wrep + WR_OUTT, 192, 2);
    wrep1x1_k<<<64,256>>>(vpost_w, wrep + WR_VPOST);

    // ht = silu(gn(mmaconv(inputs, enc_w))) ; also fills nhwcS for qpre
    mmaconv_k<<<160,256,DSMEM_TOTAL>>>(wrep + WR_ENC, nhwcS, nullptr, ht, stats + ST_HT, 1, 0, 9);
    gn_ht_fill_k<<<512,256>>>(enc_gw, enc_gb);

    // q = gn(mmaconv(ht)) + fused pool
    mmaconv_k<<<160,256,DSMEM_TOTAL>>>(wrep + WR_QPRE, nhwcS, nullptr, q, stats + ST_Q, 1, 0, 9);
    gn_apply_pool_k<<<64,256>>>(q, stats + ST_Q, qpre_gw, qpre_gb, pool);
    saconv_k<<<(BN*HWN+255)/256,256>>>(pool, qsa_w, qsa_b, qsa, BN);

    // k gn fused with pool; v GN deferred into av_fill
    gn_apply_pool_k<<<512,256>>>(k, stats + ST_K, kpre_gw, kpre_gb, pool);
    saconv_k<<<(SBN*HWN+255)/256,256>>>(pool, ksa_w, ksa_b, ksa, SBN);

    // fused attention
    attn_k<<<SBN,256>>>();
    tprob_k<<<1,32>>>();
    av_fill_k<<<512,256>>>(vpre_gw, vpre_gb);

    // att = silu(gn(mmaconv1x1(av))) + fused newout
    mmaconv_k<<<160,256,DSMEM_TOTAL>>>(wrep + WR_VPOST - 65536, nhwcS, nullptr,
                                       att, stats + ST_ATT, 1, 4, 5);
    gn_apply_att_k<<<2048,256>>>(att, stats + ST_ATT, vpost_gw, vpost_gb, mask, out);

    // o = silu(gn(mmaconv(concat(inputs, att+ht))))
    xcat_fill_k<<<512,256>>>(inputs);
    mmaconv_k<<<160,256,DSMEM_TOTAL>>>(wrep + WR_OUTT, nhwcS, nullptr, o, stats + ST_O, 2, 0, 9);
    gn_apply_k<<<2048,256>>>(o, stats + ST_O, outt_gw, outt_gb, BN, 1);

    se_k<<<BN,256>>>(se_w1, se_b1, se_w2, se_b2);
    final_k<<<2048,256>>>(out);
}

// round 14
// speedup vs baseline: 1.1679x; 1.1679x over previous
#include <cuda_runtime.h>
#include <cuda_fp16.h>
#include <cstdint>

#define BN   16
#define CH   128
#define HWN  1024
#define SN   8
#define SBN  128
#define CHW  131072

#define GUARD   64
#define RPI     1344
#define TOTROWS   (GUARD + 128*RPI + 256)
#define TOTROWS_S (GUARD + 16*RPI + 256)

// mmaconv smem (bytes): X window 200 rows x 256B, then one A buffer 32KB
#define AB_OFF 51200
#define DSMEM_TOTAL 83968

// stats slots (2 floats per img): K=0, V=256, HT=512, Q=544, ATT=576, O=608
#define ST_K   0
#define ST_V   256
#define ST_HT  512
#define ST_Q   544
#define ST_ATT 576
#define ST_O   608

__device__ float g_ht [BN*CHW];
__device__ float g_q  [BN*CHW];
__device__ float g_k  [SBN*CHW];
__device__ float g_v  [SBN*CHW];
__device__ float g_att[BN*CHW];
__device__ float g_o  [BN*CHW];
__device__ float g_stats[640];
__device__ float g_pool[(SBN+BN)*2*HWN];
__device__ float g_qsa[BN*HWN];
__device__ float g_ksa[SBN*HWN];
__device__ float g_sprob[SBN*HWN];
__device__ float g_tl[SN*BN];
__device__ float g_tp[SN*BN];
__device__ float g_peN[SN*2*CH];
__device__ float g_se3[BN*CH];
__device__ float g_Pb[SN*CH*9];
__device__ __half g_nhwc [(size_t)TOTROWS*256];
__device__ __half g_nhwcS[(size_t)TOTROWS_S*256];
// wrep single-split: kpre(294912)|vpre(294912)|qpre(147456)|outt(294912)|enc(147456)|vpost(16384)
__device__ __half g_wrep[1196032];

__device__ __forceinline__ float sigmf(float x){ return 1.f/(1.f + __expf(-x)); }
__device__ __forceinline__ bool mask_at(const unsigned char* m, int b){
    if (m[1] != 0) return m[b] != 0;
    const unsigned int* w = (const unsigned int*)m;
    return w[b] != 0;
}

__device__ __forceinline__ uint32_t smem_u32(const void* p){
    uint32_t a;
    asm("{ .reg .u64 t; cvta.to.shared.u64 t, %1; cvt.u32.u64 %0, t; }" : "=r"(a) : "l"(p));
    return a;
}
__device__ __forceinline__ void mma16816(float* d, uint32_t a0, uint32_t a1, uint32_t a2,
                                         uint32_t a3, uint32_t b0, uint32_t b1){
    asm volatile("mma.sync.aligned.m16n8k16.row.col.f32.f16.f16.f32 "
        "{%0,%1,%2,%3}, {%4,%5,%6,%7}, {%8,%9}, {%0,%1,%2,%3};"
        : "+f"(d[0]),"+f"(d[1]),"+f"(d[2]),"+f"(d[3])
        : "r"(a0),"r"(a1),"r"(a2),"r"(a3),"r"(b0),"r"(b1));
}
__device__ __forceinline__ void ldsm4(uint32_t& r0,uint32_t& r1,uint32_t& r2,uint32_t& r3,
                                      uint32_t addr){
    asm volatile("ldmatrix.sync.aligned.m8n8.x4.shared.b16 {%0,%1,%2,%3}, [%4];"
        : "=r"(r0),"=r"(r1),"=r"(r2),"=r"(r3) : "r"(addr));
}
__device__ __forceinline__ void cpa16(uint32_t d, const void* s){
    asm volatile("cp.async.cg.shared.global [%0], [%1], 16;" :: "r"(d), "l"(s));
}
__device__ __forceinline__ void cp_commit(){ asm volatile("cp.async.commit_group;" ::: "memory"); }
__device__ __forceinline__ void cp_wait0(){ asm volatile("cp.async.wait_group 0;" ::: "memory"); }

// ---- zero stats + t-logits ----
__global__ void zero_stats_k(){
    int t = threadIdx.x;
    if (t < 640) g_stats[t] = 0.f;
    else if (t < 768) g_tl[t-640] = 0.f;
}

__global__ void pe_norm_k(const float* __restrict__ pe, float* __restrict__ peN)
{
    int s = blockIdx.x, t = threadIdx.x;
    float v = pe[s*256 + t];
    float q = v*v;
    #pragma unroll
    for (int o=16;o;o>>=1) q += __shfl_down_sync(0xffffffffu, q, o);
    __shared__ float a[8];
    __shared__ float fac;
    if ((t&31)==0) a[t>>5] = q;
    __syncthreads();
    if (t==0){
        float S=0.f;
        #pragma unroll
        for (int i=0;i<8;i++) S += a[i];
        float n = sqrtf(S);
        fac = fminf(1.f, 1.f/fmaxf(n, 1e-7f));
    }
    __syncthreads();
    peN[s*256 + t] = v*fac;
}

// big buffer fill: kv concat (128 imgs, 256 ch)
__global__ void fill_nhwc_k(const float* __restrict__ hid, const float* __restrict__ oq)
{
    __shared__ float s[32][257];
    int t = threadIdx.x;
    int img = blockIdx.x>>5, y = blockIdx.x&31;
    int xg = t&31, cg = t>>5;
    size_t rb = GUARD + (size_t)img*RPI + (size_t)(y+1)*34;
    #pragma unroll
    for (int cc=0; cc<32; cc++){
        int c = cc*8 + cg;
        const float* src = (c<128) ? hid + ((size_t)img*128 + c)*1024
                                   : oq  + ((size_t)img*128 + (c-128))*1024;
        s[xg][c] = src[y*32 + xg];
    }
    __syncthreads();
    #pragma unroll
    for (int xs=0; xs<32; xs++)
        g_nhwc[(rb + xs + 1)*256 + t] = __float2half(s[xs][t]);
}

// small buffer fill: inputs (ch0-63)
__global__ void fill_in_k(const float* __restrict__ inputs)
{
    __shared__ float s[32][65];
    int t = threadIdx.x;
    int img = blockIdx.x>>5, y = blockIdx.x&31;
    int xg = t&31, cg = t>>5;
    size_t rb = GUARD + (size_t)img*RPI + (size_t)(y+1)*34;
    #pragma unroll
    for (int cc=0; cc<8; cc++){
        int c = cc*8 + cg;
        s[xg][c] = inputs[((size_t)img*64 + c)*1024 + y*32 + xg];
    }
    __syncthreads();
    if (t < 64){
        #pragma unroll
        for (int xs=0; xs<32; xs++)
            g_nhwcS[(rb + xs + 1)*256 + t] = __float2half(s[xs][t]);
    }
}

// gn(ht)+silu applied in place AND written as fp16 NHWC (ch0-127)
__global__ void gn_ht_fill_k(const float* __restrict__ gw, const float* __restrict__ gb)
{
    __shared__ float sm[32][129];
    __shared__ float sc[128], sh[128];
    int t = threadIdx.x;
    int img = blockIdx.x>>5, y = blockIdx.x&31;
    int xg = t&31, cg = t>>5;
    if (t < 128){
        float sum = g_stats[ST_HT+2*img], ssq = g_stats[ST_HT+2*img+1];
        float mu = sum*(1.f/131072.f);
        float rs = rsqrtf(ssq*(1.f/131072.f) - mu*mu + 1e-5f);
        float s_ = rs*gw[t];
        sc[t] = s_; sh[t] = gb[t] - mu*s_;
    }
    __syncthreads();
    int p = y*32 + xg;
    #pragma unroll
    for (int cc=0; cc<16; cc++){
        int c = cc*8 + cg;
        float v = g_ht[((size_t)img*128 + c)*1024 + p];
        v = v*sc[c] + sh[c];
        v *= sigmf(v);
        g_ht[((size_t)img*128 + c)*1024 + p] = v;
        sm[xg][c] = v;
    }
    __syncthreads();
    size_t rb = GUARD + (size_t)img*RPI + (size_t)(y+1)*34;
    if (t < 128){
        #pragma unroll
        for (int xs=0; xs<32; xs++)
            g_nhwcS[(rb + xs + 1)*256 + t] = __float2half(sm[xs][t]);
    }
}

// small buffer fill: concat(inputs[64], att+ht[128]) -> ch0-191
__global__ void xcat_fill_k(const float* __restrict__ inputs)
{
    __shared__ float s[32][193];
    int t = threadIdx.x;
    int img = blockIdx.x>>5, y = blockIdx.x&31;
    int xg = t&31, cg = t>>5;
    size_t rb = GUARD + (size_t)img*RPI + (size_t)(y+1)*34;
    #pragma unroll
    for (int cc=0; cc<24; cc++){
        int c = cc*8 + cg;
        float val;
        if (c < 64) val = inputs[((size_t)img*64 + c)*1024 + y*32 + xg];
        else {
            int c2 = c - 64;
            val = g_att[((size_t)img*128 + c2)*1024 + y*32 + xg]
                + g_ht [((size_t)img*128 + c2)*1024 + y*32 + xg];
        }
        s[xg][c] = val;
    }
    __syncthreads();
    if (t < 192){
        #pragma unroll
        for (int xs=0; xs<32; xs++)
            g_nhwcS[(rb + xs + 1)*256 + t] = __float2half(s[xs][t]);
    }
}

// ---- weight repack: [tap*nkc+kc][co][128k] fp16 single split; zero-pad cin ----
__global__ void wrep_k(const float* __restrict__ w, __half* __restrict__ dst,
                       int cin, int nkc)
{
    int n = nkc*147456;
    int i = blockIdx.x*blockDim.x + threadIdx.x;
    if (i >= n) return;
    int kl = i & 127;
    int r = i >> 7;
    int co = r & 127; r >>= 7;
    int kc = r % nkc;
    int tap = r / nkc;
    int cin_idx = kc*128 + kl;
    float val = (cin_idx < cin) ? w[((size_t)co*cin + cin_idx)*9 + tap] : 0.f;
    dst[((tap*nkc+kc)*128 + co)*128 + kl] = __float2half(val);
}

__global__ void wrep1x1_k(const float* __restrict__ w, __half* __restrict__ dst)
{
    int i = blockIdx.x*blockDim.x + threadIdx.x;
    if (i < 16384) dst[i] = __float2half(w[i]);
}

// ---- pe correction with border masks ----
__global__ void pbconv_k(const float* __restrict__ w)
{
    int s = blockIdx.x, co = threadIdx.x;
    float P[9];
    #pragma unroll
    for (int tap=0;tap<9;tap++){
        float acc = 0.f;
        for (int c=0;c<256;c++)
            acc += g_peN[s*256 + c] * w[((size_t)co*256 + c)*9 + tap];
        P[tap] = acc;
    }
    #pragma unroll
    for (int yc=0;yc<3;yc++){
        #pragma unroll
        for (int xc=0;xc<3;xc++){
            float tot = 0.f;
            #pragma unroll
            for (int dy=0;dy<3;dy++){
                if ((yc==0 && dy==0) || (yc==2 && dy==2)) continue;
                float rs = P[dy*3+1];
                if (xc!=0) rs += P[dy*3+0];
                if (xc!=2) rs += P[dy*3+2];
                tot += rs;
            }
            g_Pb[(s*128+co)*9 + yc*3+xc] = tot;
        }
    }
}

// ---- per-tap MMA (round-12 single-stage version) ----
__device__ __forceinline__ void conv_tap(uint32_t xb, uint32_t ab, int tap,
                                         int lane, int cob, int pxb,
                                         float acc[4][4][4])
{
    const int lr  = lane & 7;
    const int hsA = lane >> 4;
    const int hsB = (lane >> 3) & 1;
    const int dy = tap/3, dx = tap - dy*3;
    const int dlt = (dy-1)*34 + (dx-1);

    uint32_t rowA[4], rsA[4];
    #pragma unroll
    for (int mi=0;mi<4;mi++){
        int r = cob + mi*16 + lr + ((lane>>3)&1)*8;
        rowA[mi] = (uint32_t)r*256u; rsA[mi] = (uint32_t)(r&7);
    }
    uint32_t rowB[2], rsB[2];
    #pragma unroll
    for (int nn=0;nn<2;nn++){
        int r = 36 + dlt + pxb + nn*16 + lr + (lane>>4)*8;
        rowB[nn] = (uint32_t)r*256u; rsB[nn] = (uint32_t)(r&7);
    }
    #pragma unroll
    for (int k8=0;k8<8;k8++){
        uint32_t a[4][4];
        #pragma unroll
        for (int mi=0;mi<4;mi++){
            uint32_t sgi = (uint32_t)(k8*2 + hsA);
            ldsm4(a[mi][0],a[mi][1],a[mi][2],a[mi][3],
                  ab + rowA[mi] + ((sgi ^ rsA[mi])<<4));
        }
        #pragma unroll
        for (int nn=0;nn<2;nn++){
            uint32_t sgi = (uint32_t)(k8*2 + hsB);
            uint32_t b0,b1,b2,b3;
            ldsm4(b0,b1,b2,b3, xb + rowB[nn] + ((sgi ^ rsB[nn])<<4));
            #pragma unroll
            for (int mi=0;mi<4;mi++){
                mma16816(acc[mi][2*nn],   a[mi][0],a[mi][1],a[mi][2],a[mi][3], b0,b1);
                mma16816(acc[mi][2*nn+1], a[mi][0],a[mi][1],a[mi][2],a[mi][3], b2,b3);
            }
        }
    }
}

// ---- mma.sync fp16 implicit conv: D[128co,128px], 2 CTAs/SM, fused GN sums ----
__global__ __launch_bounds__(256,2)
void mmaconv_k(const __half* __restrict__ wrep,
               const __half* __restrict__ nhwc,
               const float* __restrict__ Pb,
               float* __restrict__ dst,
               float* __restrict__ stats, int nkc, int t0, int t1)
{
    extern __shared__ char dsm[];
    const uint32_t sb = smem_u32(dsm);
    const uint32_t XB = sb;
    const uint32_t AB = sb + AB_OFF;
    const int t = threadIdx.x;
    const int wid = t>>5, lane = t&31;
    const int img = blockIdx.x/10;
    const int p0  = (blockIdx.x%10)*128;
    const int s   = img>>4;
    const int cob = (wid&1)*64;
    const int pxb = (wid>>1)*32;

    float acc[4][4][4];
    #pragma unroll
    for (int mi=0;mi<4;mi++)
    #pragma unroll
    for (int ni=0;ni<4;ni++)
    #pragma unroll
    for (int e=0;e<4;e++) acc[mi][ni][e]=0.f;

    for (int kc=0; kc<nkc; kc++){
        {
            const char* src = (const char*)nhwc
                + ((size_t)GUARD + (size_t)img*RPI + p0 - 36)*512 + kc*256;
            #pragma unroll
            for (int j=0;j<13;j++){
                int i = j*256 + t;
                if (i < 3200){
                    uint32_t r = (uint32_t)(i>>4), sg = (uint32_t)(i&15);
                    cpa16(XB + r*256 + ((sg^(r&7))<<4), src + (size_t)r*512 + sg*16);
                }
            }
            cp_commit();
        }
        for (int tap=t0; tap<t1; tap++){
            const char* asrc = (const char*)(wrep + (size_t)(tap*nkc+kc)*16384);
            #pragma unroll
            for (int j=0;j<8;j++){
                int i = j*256 + t;
                uint32_t r = (uint32_t)(i>>4), sg = (uint32_t)(i&15);
                cpa16(AB + r*256 + ((sg^(r&7))<<4), asrc + (size_t)i*16);
            }
            cp_commit(); cp_wait0(); __syncthreads();
            conv_tap(XB, AB, tap, lane, cob, pxb, acc);
            __syncthreads();
        }
    }

    const int g  = lane>>2;
    const int t2 = (lane&3)*2;
    float sm_=0.f, sq_=0.f;
    #pragma unroll
    for (int mi=0;mi<4;mi++){
        #pragma unroll
        for (int n8=0;n8<4;n8++){
            #pragma unroll
            for (int e=0;e<4;e++){
                int co  = cob + mi*16 + g + ((e>>1)<<3);
                int col = pxb + n8*8 + t2 + (e&1);
                int pp  = p0 + col;
                int q34 = pp/34;
                int yy  = q34 - 1;
                int xx  = pp - q34*34 - 1;
                if ((unsigned)yy < 32u && (unsigned)xx < 32u){
                    float v = acc[mi][n8][e];
                    if (Pb){
                        int yc = (yy==0)?0:((yy==31)?2:1);
                        int xc = (xx==0)?0:((xx==31)?2:1);
                        v += Pb[(s*128+co)*9 + yc*3+xc];
                    }
                    dst[((size_t)img*128+co)*1024 + (yy<<5)+xx] = v;
                    sm_ += v; sq_ += v*v;
                }
            }
        }
    }
    #pragma unroll
    for (int o=16;o;o>>=1){
        sm_ += __shfl_down_sync(0xffffffffu, sm_, o);
        sq_ += __shfl_down_sync(0xffffffffu, sq_, o);
    }
    float* red = (float*)dsm;
    __syncthreads();
    if (lane==0){ red[wid*2] = sm_; red[wid*2+1] = sq_; }
    __syncthreads();
    if (t==0){
        float S=0.f, S2=0.f;
        #pragma unroll
        for (int w=0;w<8;w++){ S += red[w*2]; S2 += red[w*2+1]; }
        atomicAdd(&stats[img*2],   S);
        atomicAdd(&stats[img*2+1], S2);
    }
}

// ---- GN apply from raw sums (o) ----
__global__ void gn_apply_k(float* __restrict__ x, const float* __restrict__ stats,
                           const float* __restrict__ gw, const float* __restrict__ gb,
                           int nimg, int act)
{
    int n4 = nimg*32768;
    for (int i = blockIdx.x*blockDim.x + threadIdx.x; i < n4; i += gridDim.x*blockDim.x){
        int base = i<<2;
        int img = base>>17; int c = (base>>10)&127;
        float sum = stats[2*img], ssq = stats[2*img+1];
        float mu = sum*(1.f/131072.f);
        float rs = rsqrtf(ssq*(1.f/131072.f) - mu*mu + 1e-5f);
        float sc = rs*gw[c];
        float sh = gb[c] - mu*sc;
        float4 v = ((float4*)x)[i];
        v.x = v.x*sc+sh; v.y = v.y*sc+sh; v.z = v.z*sc+sh; v.w = v.w*sc+sh;
        if (act){
            v.x *= sigmf(v.x); v.y *= sigmf(v.y); v.z *= sigmf(v.z); v.w *= sigmf(v.w);
        }
        ((float4*)x)[i] = v;
    }
}

// ---- GN apply + channel mean/max pool fused (k, q) ----
__global__ void gn_apply_pool_k(float* __restrict__ x, const float* __restrict__ stats,
                                const float* __restrict__ gw, const float* __restrict__ gb,
                                float* __restrict__ pool)
{
    __shared__ float sc[128], sh[128];
    int t = threadIdx.x;
    int img = blockIdx.x>>2;
    int p = ((blockIdx.x&3)<<8) + t;
    if (t < 128){
        float sum = stats[2*img], ssq = stats[2*img+1];
        float mu = sum*(1.f/131072.f);
        float rs = rsqrtf(ssq*(1.f/131072.f) - mu*mu + 1e-5f);
        float scv = rs*gw[t];
        sc[t] = scv; sh[t] = gb[t] - mu*scv;
    }
    __syncthreads();
    float* base = x + (size_t)img*CHW + p;
    float s = 0.f, m = -3.402823466e38f;
    #pragma unroll 4
    for (int c=0;c<128;c++){
        float y = base[(size_t)c<<10]*sc[c] + sh[c];
        base[(size_t)c<<10] = y;
        s += y; m = fmaxf(m, y);
    }
    pool[img*2048 + p]        = s*(1.f/128.f);
    pool[img*2048 + 1024 + p] = m;
}

// ---- GN apply att (silu) + newout write fused ----
__global__ void gn_apply_att_k(float* __restrict__ x, const float* __restrict__ stats,
                               const float* __restrict__ gw, const float* __restrict__ gb,
                               const unsigned char* __restrict__ mask,
                               float* __restrict__ out)
{
    int i = blockIdx.x*blockDim.x + threadIdx.x;
    if (i >= BN*32768) return;
    int base = i<<2;
    int img = base>>17; int c = (base>>10)&127;
    float sum = stats[2*img], ssq = stats[2*img+1];
    float mu = sum*(1.f/131072.f);
    float rs = rsqrtf(ssq*(1.f/131072.f) - mu*mu + 1e-5f);
    float sc = rs*gw[c];
    float sh = gb[c] - mu*sc;
    float4 v = ((float4*)x)[i];
    v.x = v.x*sc+sh; v.y = v.y*sc+sh; v.z = v.z*sc+sh; v.w = v.w*sc+sh;
    v.x *= sigmf(v.x); v.y *= sigmf(v.y); v.z *= sigmf(v.z); v.w *= sigmf(v.w);
    ((float4*)x)[i] = v;
    float4 z = mask_at(mask, img) ? v : make_float4(0.f,0.f,0.f,0.f);
    *(float4*)&out[(size_t)2*BN*CHW + base] = z;
}

// ---- 2->1 3x3 conv + sigmoid ----
__global__ void saconv_k(const float* __restrict__ pool, const float* __restrict__ w,
                         const float* __restrict__ b, float* __restrict__ sa, int nimg)
{
    int i = blockIdx.x*blockDim.x + threadIdx.x;
    if (i >= nimg*HWN) return;
    int img = i>>10, p = i&1023, y = p>>5, x = p&31;
    float acc = b[0];
    #pragma unroll
    for (int c2=0;c2<2;c2++)
    #pragma unroll
    for (int dy=-1;dy<=1;dy++)
    #pragma unroll
    for (int dx=-1;dx<=1;dx++){
        int yy=y+dy, xx=x+dx;
        if ((unsigned)yy<32u && (unsigned)xx<32u)
            acc += pool[img*2048 + c2*1024 + (yy<<5)+xx] * w[c2*9 + (dy+1)*3 + (dx+1)];
    }
    sa[i] = sigmf(acc);
}

// ---- attention pieces (round-12 versions) ----
__global__ void qfg_k(float* __restrict__ qfg)
{
    int wid  = (blockIdx.x*blockDim.x + threadIdx.x) >> 5;
    int lane = threadIdx.x & 31;
    if (wid >= SN*BN*CH) return;
    int c = wid & 127, b = (wid>>7)&15, s = wid>>11;
    const float* qp = g_q   + ((size_t)b*128 + c)*1024;
    const float* kp = g_ksa + (size_t)(s*16+b)*1024;
    float acc = 0.f;
    for (int p=lane; p<1024; p+=32) acc += qp[p]*kp[p];
    #pragma unroll
    for (int o=16;o;o>>=1) acc += __shfl_down_sync(0xffffffffu, acc, o);
    if (!lane) qfg[wid] = acc*(1.f/1024.f);
}

__global__ void sprob_k(const float* __restrict__ qfg)
{
    int img = blockIdx.x;
    __shared__ float fq[128];
    int t = threadIdx.x;
    if (t < 128) fq[t] = qfg[img*128 + t];
    __syncthreads();
    for (int p=t; p<1024; p+=256){
        const float* kp = g_k + (size_t)img*CHW + p;
        float acc = 0.f;
        #pragma unroll 4
        for (int c=0;c<128;c++) acc += fq[c]*kp[(size_t)c<<10];
        g_sprob[img*1024 + p] = sigmf(acc);
    }
}

// 1024 blocks: img x 8 chunks, atomic accumulate
__global__ void tlogit_k()
{
    int img = blockIdx.x>>3, chunk = blockIdx.x&7, b = img & 15;
    int base = chunk*16384;
    float acc = 0.f;
    for (int i = base + threadIdx.x; i < base + 16384; i += 256){
        int p = i & 1023;
        acc += g_q[(size_t)b*CHW + i]*g_qsa[b*1024+p]
             * g_k[(size_t)img*CHW + i]*g_ksa[img*1024+p];
    }
    #pragma unroll
    for (int o=16;o;o>>=1) acc += __shfl_down_sync(0xffffffffu, acc, o);
    __shared__ float sh[8];
    if ((threadIdx.x&31)==0) sh[threadIdx.x>>5] = acc;
    __syncthreads();
    if (threadIdx.x==0){
        float S=0.f;
        #pragma unroll
        for (int i=0;i<8;i++) S += sh[i];
        atomicAdd(&g_tl[img], S);
    }
}

__global__ void tprob_k()
{
    int b = threadIdx.x;
    if (b >= 16) return;
    const float SCL = rsqrtf(131072.f);
    float m = -3.402823466e38f;
    #pragma unroll
    for (int s=0;s<8;s++) m = fmaxf(m, g_tl[s*16+b]*SCL);
    float e[8]; float sum = 0.f;
    #pragma unroll
    for (int s=0;s<8;s++){ e[s] = __expf(g_tl[s*16+b]*SCL - m); sum += e[s]; }
    float inv = 1.f/sum;
    #pragma unroll
    for (int s=0;s<8;s++) g_tp[s*16+b] = e[s]*inv;
}

// ---- av with fused v-GN, writes fp16 NHWC directly ----
__global__ void av_fill_k(const float* __restrict__ vgw, const float* __restrict__ vgb)
{
    __shared__ float sm[32][129];
    __shared__ float sc[8][128], sh[8][128];
    int t = threadIdx.x;
    int img = blockIdx.x>>5, y = blockIdx.x&31;
    int xg = t&31, cg = t>>5;
    if (t < 128){
        #pragma unroll
        for (int s=0;s<8;s++){
            int i2 = s*16 + img;
            float sum = g_stats[ST_V+2*i2], ssq = g_stats[ST_V+2*i2+1];
            float mu = sum*(1.f/131072.f);
            float rs = rsqrtf(ssq*(1.f/131072.f) - mu*mu + 1e-5f);
            float s_ = rs*vgw[t];
            sc[s][t] = s_; sh[s][t] = vgb[t] - mu*s_;
        }
    }
    __syncthreads();
    int p = y*32 + xg;
    float ws[8];
    #pragma unroll
    for (int s=0;s<8;s++){
        int i2 = s*16 + img;
        ws[s] = g_tp[i2]*g_sprob[i2*1024 + p];
    }
    #pragma unroll
    for (int cc=0; cc<16; cc++){
        int c = cc*8 + cg;
        float acc = 0.f;
        #pragma unroll
        for (int s=0;s<8;s++){
            int i2 = s*16 + img;
            float vv = g_v[((size_t)i2*128 + c)*1024 + p];
            acc += ws[s]*(vv*sc[s][c] + sh[s][c]);
        }
        sm[xg][c] = acc;
    }
    __syncthreads();
    size_t rb = GUARD + (size_t)img*RPI + (size_t)(y+1)*34;
    if (t < 128){
        #pragma unroll
        for (int xs=0; xs<32; xs++)
            g_nhwcS[(rb + xs + 1)*256 + t] = __float2half(sm[xs][t]);
    }
}

// ---- fused SE ----
__global__ void se_k(const float* __restrict__ w1, const float* __restrict__ b1,
                     const float* __restrict__ w2, const float* __restrict__ b2)
{
    __shared__ float mean[128], f1[32];
    int b = blockIdx.x;
    int w = threadIdx.x>>5, lane = threadIdx.x&31;
    for (int c=w; c<128; c+=8){
        const float* p = g_o + ((size_t)b*128 + c)*1024;
        float s = 0.f;
        for (int i=lane; i<1024; i+=32) s += p[i];
        #pragma unroll
        for (int o=16;o;o>>=1) s += __shfl_down_sync(0xffffffffu, s, o);
        if (!lane) mean[c] = s*(1.f/1024.f);
    }
    __syncthreads();
    if (threadIdx.x < 32){
        int j = threadIdx.x;
        float acc = b1[j];
        #pragma unroll 4
        for (int c=0;c<128;c++) acc += mean[c]*w1[j*128+c];
        f1[j] = fmaxf(acc, 0.f);
    }
    __syncthreads();
    if (threadIdx.x < 128){
        int c = threadIdx.x;
        float acc = b2[c];
        #pragma unroll
        for (int j=0;j<32;j++) acc += f1[j]*w2[c*32+j];
        g_se3[b*128+c] = sigmf(acc);
    }
}

__global__ void final_k(float* __restrict__ out)
{
    int i = blockIdx.x*blockDim.x + threadIdx.x;
    if (i >= BN*CHW/4) return;
    int base = i<<2;
    int b = base>>17; int c = (base>>10)&127;
    float g = 1.f + g_se3[b*128+c];
    float4 o4 = *(const float4*)&g_o[base];
    o4.x*=g; o4.y*=g; o4.z*=g; o4.w*=g;
    *(float4*)&out[base] = o4;
    *(float4*)&out[(size_t)BN*CHW + base] = *(const float4*)&g_ht[base];
}

// reuse g_Pb tail region? no — dedicated qfg scratch
__device__ float g_qfg[SN*BN*CH];

// ---- host launcher ----
extern "C" void kernel_launch(void* const* d_in, const int* in_sizes, int n_in,
                              void* d_out, int out_size)
{
    (void)in_sizes; (void)n_in; (void)out_size;
    const float* inputs  = (const float*)d_in[0];
    const float* hidden  = (const float*)d_in[1];
    const float* outq    = (const float*)d_in[2];
    const unsigned char* mask = (const unsigned char*)d_in[3];
    const float* enc_w   = (const float*)d_in[4];
    const float* enc_gw  = (const float*)d_in[5];
    const float* enc_gb  = (const float*)d_in[6];
    const float* qpre_w  = (const float*)d_in[7];
    const float* qpre_gw = (const float*)d_in[8];
    const float* qpre_gb = (const float*)d_in[9];
    const float* kpre_w  = (const float*)d_in[10];
    const float* kpre_gw = (const float*)d_in[11];
    const float* kpre_gb = (const float*)d_in[12];
    const float* vpre_w  = (const float*)d_in[13];
    const float* vpre_gw = (const float*)d_in[14];
    const float* vpre_gb = (const float*)d_in[15];
    const float* qsa_w   = (const float*)d_in[16];
    const float* qsa_b   = (const float*)d_in[17];
    const float* ksa_w   = (const float*)d_in[18];
    const float* ksa_b   = (const float*)d_in[19];
    const float* vpost_w = (const float*)d_in[20];
    const float* vpost_gw= (const float*)d_in[21];
    const float* vpost_gb= (const float*)d_in[22];
    const float* pos_emb = (const float*)d_in[23];
    const float* outt_w  = (const float*)d_in[24];
    const float* outt_gw = (const float*)d_in[25];
    const float* outt_gb = (const float*)d_in[26];
    const float* se_w1   = (const float*)d_in[27];
    const float* se_b1   = (const float*)d_in[28];
    const float* se_w2   = (const float*)d_in[29];
    const float* se_b2   = (const float*)d_in[30];
    float* out = (float*)d_out;

    float *ht,*q,*k,*v,*att,*o,*stats,*pool,*qsa,*ksa,*peN,*Pb,*qfg;
    __half *wrep, *nhwc, *nhwcS;
    cudaGetSymbolAddress((void**)&ht,   g_ht);
    cudaGetSymbolAddress((void**)&q,    g_q);
    cudaGetSymbolAddress((void**)&k,    g_k);
    cudaGetSymbolAddress((void**)&v,    g_v);
    cudaGetSymbolAddress((void**)&att,  g_att);
    cudaGetSymbolAddress((void**)&o,    g_o);
    cudaGetSymbolAddress((void**)&stats,g_stats);
    cudaGetSymbolAddress((void**)&pool, g_pool);
    cudaGetSymbolAddress((void**)&qsa,  g_qsa);
    cudaGetSymbolAddress((void**)&ksa,  g_ksa);
    cudaGetSymbolAddress((void**)&peN,  g_peN);
    cudaGetSymbolAddress((void**)&Pb,   g_Pb);
    cudaGetSymbolAddress((void**)&qfg,  g_qfg);
    cudaGetSymbolAddress((void**)&wrep, g_wrep);
    cudaGetSymbolAddress((void**)&nhwc, g_nhwc);
    cudaGetSymbolAddress((void**)&nhwcS,g_nhwcS);

    const size_t WR_KPRE  = 0;
    const size_t WR_VPRE  = 294912;
    const size_t WR_QPRE  = 589824;
    const size_t WR_OUTT  = 737280;
    const size_t WR_ENC   = 1032192;
    const size_t WR_VPOST = 1179648;   // accessed as slot 4 via -4*16384 base

    cudaFuncSetAttribute(mmaconv_k, cudaFuncAttributeMaxDynamicSharedMemorySize, DSMEM_TOTAL);

    // persistent side stream + fork/join events (created once; reused across calls)
    static cudaStream_t s1 = nullptr;
    static cudaEvent_t evA = nullptr, evB = nullptr;
    if (!s1){
        cudaStreamCreateWithFlags(&s1, cudaStreamNonBlocking);
        cudaEventCreateWithFlags(&evA, cudaEventDisableTiming);
        cudaEventCreateWithFlags(&evB, cudaEventDisableTiming);
    }

    zero_stats_k<<<1,768>>>();
    cudaEventRecord(evA, 0);
    cudaStreamWaitEvent(s1, evA, 0);

    // ---- side stream: enc -> ht -> qpre -> q pool/saconv (q pool at +128 imgs) ----
    fill_in_k<<<512,256,0,s1>>>(inputs);
    wrep_k<<<576,256,0,s1>>>(enc_w,  wrep + WR_ENC,  64, 1);
    wrep_k<<<576,256,0,s1>>>(qpre_w, wrep + WR_QPRE, 128, 1);
    wrep_k<<<1152,256,0,s1>>>(outt_w, wrep + WR_OUTT, 192, 2);
    wrep1x1_k<<<64,256,0,s1>>>(vpost_w, wrep + WR_VPOST);
    mmaconv_k<<<160,256,DSMEM_TOTAL,s1>>>(wrep + WR_ENC, nhwcS, nullptr, ht,
                                          stats + ST_HT, 1, 0, 9);
    gn_ht_fill_k<<<512,256,0,s1>>>(enc_gw, enc_gb);
    mmaconv_k<<<160,256,DSMEM_TOTAL,s1>>>(wrep + WR_QPRE, nhwcS, nullptr, q,
                                          stats + ST_Q, 1, 0, 9);
    gn_apply_pool_k<<<64,256,0,s1>>>(q, stats + ST_Q, qpre_gw, qpre_gb, pool + 128*2048);
    saconv_k<<<(BN*HWN+255)/256,256,0,s1>>>(pool + 128*2048, qsa_w, qsa_b, qsa, BN);

    // ---- main stream: kv path ----
    fill_nhwc_k<<<4096,256>>>(hidden, outq);
    wrep_k<<<1152,256>>>(kpre_w, wrep + WR_KPRE, 256, 2);
    mmaconv_k<<<1280,256,DSMEM_TOTAL>>>(wrep + WR_KPRE, nhwc, nullptr, k, stats + ST_K, 2, 0, 9);
    wrep_k<<<1152,256>>>(vpre_w, wrep + WR_VPRE, 256, 2);
    pe_norm_k<<<8,256>>>(pos_emb, peN);
    pbconv_k<<<8,128>>>(vpre_w);
    mmaconv_k<<<1280,256,DSMEM_TOTAL>>>(wrep + WR_VPRE, nhwc, Pb, v, stats + ST_V, 2, 0, 9);
    gn_apply_pool_k<<<512,256>>>(k, stats + ST_K, kpre_gw, kpre_gb, pool);
    saconv_k<<<(SBN*HWN+255)/256,256>>>(pool, ksa_w, ksa_b, ksa, SBN);

    // ---- join ----
    cudaEventRecord(evB, s1);
    cudaStreamWaitEvent(0, evB, 0);

    // attention
    qfg_k<<<2048,256>>>(qfg);
    sprob_k<<<SBN,256>>>(qfg);
    tlogit_k<<<1024,256>>>();
    tprob_k<<<1,32>>>();
    av_fill_k<<<512,256>>>(vpre_gw, vpre_gb);

    // att = silu(gn(mmaconv1x1(av))) + fused newout
    mmaconv_k<<<160,256,DSMEM_TOTAL>>>(wrep + WR_VPOST - 65536, nhwcS, nullptr,
                                       att, stats + ST_ATT, 1, 4, 5);
    gn_apply_att_k<<<2048,256>>>(att, stats + ST_ATT, vpost_gw, vpost_gb, mask, out);

    // o = silu(gn(mmaconv(concat(inputs, att+ht))))
    xcat_fill_k<<<512,256>>>(inputs);
    mmaconv_k<<<160,256,DSMEM_TOTAL>>>(wrep + WR_OUTT, nhwcS, nullptr, o, stats + ST_O, 2, 0, 9);
    gn_apply_k<<<2048,256>>>(o, stats + ST_O, outt_gw, outt_gb, BN, 1);

    se_k<<<BN,256>>>(se_w1, se_b1, se_w2, se_b2);
    final_k<<<2048,256>>>(out);
}

// round 15
// speedup vs baseline: 1.3776x; 1.1796x over previous
#include <cuda_runtime.h>
#include <cuda_fp16.h>
#include <cstdint>

#define BN   16
#define CH   128
#define HWN  1024
#define SN   8
#define SBN  128
#define CHW  131072

#define GUARD   64
#define RPI     1344
#define TOTROWS   (GUARD + 128*RPI + 256)
#define TOTROWS_S (GUARD + 16*RPI + 256)

#define AB_OFF 51200
#define DSMEM_TOTAL 83968

// stats slots (2 floats per img): K=0, V=256, HT=512, Q=544, ATT=576, O=608
#define ST_K   0
#define ST_V   256
#define ST_HT  512
#define ST_Q   544
#define ST_ATT 576
#define ST_O   608

__device__ float g_ht [BN*CHW];
__device__ float g_q  [BN*CHW];
__device__ float g_k  [SBN*CHW];
__device__ float g_v  [SBN*CHW];
__device__ float g_att[BN*CHW];
__device__ float g_o  [BN*CHW];
__device__ float g_stats[640];
__device__ float g_pool[(SBN+BN)*2*HWN];
__device__ float g_qsa[BN*HWN];
__device__ float g_ksa[SBN*HWN];
__device__ float g_sprob[SBN*HWN];
__device__ float g_tl[SN*BN];
__device__ float g_tp[SN*BN];
__device__ float g_peN[SN*2*CH];
__device__ float g_se3[BN*CH];
__device__ float g_Pb[SN*CH*9];
__device__ float g_qfg[SN*BN*CH];
__device__ __half g_nhwc [(size_t)TOTROWS*256];
__device__ __half g_nhwcS[(size_t)TOTROWS_S*256];
// wrep single-split: kpre(294912)|vpre(294912)|qpre(147456)|outt(294912)|enc(147456)|vpost(16384)
__device__ __half g_wrep[1196032];

__device__ __forceinline__ float sigmf(float x){ return 1.f/(1.f + __expf(-x)); }
__device__ __forceinline__ bool mask_at(const unsigned char* m, int b){
    if (m[1] != 0) return m[b] != 0;
    const unsigned int* w = (const unsigned int*)m;
    return w[b] != 0;
}

__device__ __forceinline__ uint32_t smem_u32(const void* p){
    uint32_t a;
    asm("{ .reg .u64 t; cvta.to.shared.u64 t, %1; cvt.u32.u64 %0, t; }" : "=r"(a) : "l"(p));
    return a;
}
__device__ __forceinline__ void mma16816(float* d, uint32_t a0, uint32_t a1, uint32_t a2,
                                         uint32_t a3, uint32_t b0, uint32_t b1){
    asm volatile("mma.sync.aligned.m16n8k16.row.col.f32.f16.f16.f32 "
        "{%0,%1,%2,%3}, {%4,%5,%6,%7}, {%8,%9}, {%0,%1,%2,%3};"
        : "+f"(d[0]),"+f"(d[1]),"+f"(d[2]),"+f"(d[3])
        : "r"(a0),"r"(a1),"r"(a2),"r"(a3),"r"(b0),"r"(b1));
}
__device__ __forceinline__ void ldsm4(uint32_t& r0,uint32_t& r1,uint32_t& r2,uint32_t& r3,
                                      uint32_t addr){
    asm volatile("ldmatrix.sync.aligned.m8n8.x4.shared.b16 {%0,%1,%2,%3}, [%4];"
        : "=r"(r0),"=r"(r1),"=r"(r2),"=r"(r3) : "r"(addr));
}
__device__ __forceinline__ void cpa16(uint32_t d, const void* s){
    asm volatile("cp.async.cg.shared.global [%0], [%1], 16;" :: "r"(d), "l"(s));
}
__device__ __forceinline__ void cp_commit(){ asm volatile("cp.async.commit_group;" ::: "memory"); }
__device__ __forceinline__ void cp_wait0(){ asm volatile("cp.async.wait_group 0;" ::: "memory"); }

// ---- zero stats + t-logits ----
__global__ void zero_stats_k(){
    int t = threadIdx.x;
    if (t < 640) g_stats[t] = 0.f;
    else if (t < 768) g_tl[t-640] = 0.f;
}

__global__ void pe_norm_k(const float* __restrict__ pe, float* __restrict__ peN)
{
    int s = blockIdx.x, t = threadIdx.x;
    float v = pe[s*256 + t];
    float q = v*v;
    #pragma unroll
    for (int o=16;o;o>>=1) q += __shfl_down_sync(0xffffffffu, q, o);
    __shared__ float a[8];
    __shared__ float fac;
    if ((t&31)==0) a[t>>5] = q;
    __syncthreads();
    if (t==0){
        float S=0.f;
        #pragma unroll
        for (int i=0;i<8;i++) S += a[i];
        float n = sqrtf(S);
        fac = fminf(1.f, 1.f/fmaxf(n, 1e-7f));
    }
    __syncthreads();
    peN[s*256 + t] = v*fac;
}

// big buffer fill: kv concat (128 imgs, 256 ch)
__global__ void fill_nhwc_k(const float* __restrict__ hid, const float* __restrict__ oq)
{
    __shared__ float s[32][257];
    int t = threadIdx.x;
    int img = blockIdx.x>>5, y = blockIdx.x&31;
    int xg = t&31, cg = t>>5;
    size_t rb = GUARD + (size_t)img*RPI + (size_t)(y+1)*34;
    #pragma unroll
    for (int cc=0; cc<32; cc++){
        int c = cc*8 + cg;
        const float* src = (c<128) ? hid + ((size_t)img*128 + c)*1024
                                   : oq  + ((size_t)img*128 + (c-128))*1024;
        s[xg][c] = src[y*32 + xg];
    }
    __syncthreads();
    #pragma unroll
    for (int xs=0; xs<32; xs++)
        g_nhwc[(rb + xs + 1)*256 + t] = __float2half(s[xs][t]);
}

// small buffer fill: inputs (ch0-63)
__global__ void fill_in_k(const float* __restrict__ inputs)
{
    __shared__ float s[32][65];
    int t = threadIdx.x;
    int img = blockIdx.x>>5, y = blockIdx.x&31;
    int xg = t&31, cg = t>>5;
    size_t rb = GUARD + (size_t)img*RPI + (size_t)(y+1)*34;
    #pragma unroll
    for (int cc=0; cc<8; cc++){
        int c = cc*8 + cg;
        s[xg][c] = inputs[((size_t)img*64 + c)*1024 + y*32 + xg];
    }
    __syncthreads();
    if (t < 64){
        #pragma unroll
        for (int xs=0; xs<32; xs++)
            g_nhwcS[(rb + xs + 1)*256 + t] = __float2half(s[xs][t]);
    }
}

// gn(ht)+silu in place AND written as fp16 NHWC (ch0-127)
__global__ void gn_ht_fill_k(const float* __restrict__ gw, const float* __restrict__ gb)
{
    __shared__ float sm[32][129];
    __shared__ float sc[128], sh[128];
    int t = threadIdx.x;
    int img = blockIdx.x>>5, y = blockIdx.x&31;
    int xg = t&31, cg = t>>5;
    if (t < 128){
        float sum = g_stats[ST_HT+2*img], ssq = g_stats[ST_HT+2*img+1];
        float mu = sum*(1.f/131072.f);
        float rs = rsqrtf(ssq*(1.f/131072.f) - mu*mu + 1e-5f);
        float s_ = rs*gw[t];
        sc[t] = s_; sh[t] = gb[t] - mu*s_;
    }
    __syncthreads();
    int p = y*32 + xg;
    #pragma unroll
    for (int cc=0; cc<16; cc++){
        int c = cc*8 + cg;
        float v = g_ht[((size_t)img*128 + c)*1024 + p];
        v = v*sc[c] + sh[c];
        v *= sigmf(v);
        g_ht[((size_t)img*128 + c)*1024 + p] = v;
        sm[xg][c] = v;
    }
    __syncthreads();
    size_t rb = GUARD + (size_t)img*RPI + (size_t)(y+1)*34;
    if (t < 128){
        #pragma unroll
        for (int xs=0; xs<32; xs++)
            g_nhwcS[(rb + xs + 1)*256 + t] = __float2half(sm[xs][t]);
    }
}

// small buffer fill: concat(inputs[64], att+ht[128]) -> ch0-191
__global__ void xcat_fill_k(const float* __restrict__ inputs)
{
    __shared__ float s[32][193];
    int t = threadIdx.x;
    int img = blockIdx.x>>5, y = blockIdx.x&31;
    int xg = t&31, cg = t>>5;
    size_t rb = GUARD + (size_t)img*RPI + (size_t)(y+1)*34;
    #pragma unroll
    for (int cc=0; cc<24; cc++){
        int c = cc*8 + cg;
        float val;
        if (c < 64) val = inputs[((size_t)img*64 + c)*1024 + y*32 + xg];
        else {
            int c2 = c - 64;
            val = g_att[((size_t)img*128 + c2)*1024 + y*32 + xg]
                + g_ht [((size_t)img*128 + c2)*1024 + y*32 + xg];
        }
        s[xg][c] = val;
    }
    __syncthreads();
    if (t < 192){
        #pragma unroll
        for (int xs=0; xs<32; xs++)
            g_nhwcS[(rb + xs + 1)*256 + t] = __float2half(s[xs][t]);
    }
}

// ---- weight repack: [tap*nkc+kc][co][128k] fp16 single split; zero-pad cin ----
__global__ void wrep_k(const float* __restrict__ w, __half* __restrict__ dst,
                       int cin, int nkc)
{
    int n = nkc*147456;
    int i = blockIdx.x*blockDim.x + threadIdx.x;
    if (i >= n) return;
    int kl = i & 127;
    int r = i >> 7;
    int co = r & 127; r >>= 7;
    int kc = r % nkc;
    int tap = r / nkc;
    int cin_idx = kc*128 + kl;
    float val = (cin_idx < cin) ? w[((size_t)co*cin + cin_idx)*9 + tap] : 0.f;
    dst[((tap*nkc+kc)*128 + co)*128 + kl] = __float2half(val);
}

__global__ void wrep1x1_k(const float* __restrict__ w, __half* __restrict__ dst)
{
    int i = blockIdx.x*blockDim.x + threadIdx.x;
    if (i < 16384) dst[i] = __float2half(w[i]);
}

// ---- pe correction with border masks ----
__global__ void pbconv_k(const float* __restrict__ w)
{
    int s = blockIdx.x, co = threadIdx.x;
    float P[9];
    #pragma unroll
    for (int tap=0;tap<9;tap++){
        float acc = 0.f;
        for (int c=0;c<256;c++)
            acc += g_peN[s*256 + c] * w[((size_t)co*256 + c)*9 + tap];
        P[tap] = acc;
    }
    #pragma unroll
    for (int yc=0;yc<3;yc++){
        #pragma unroll
        for (int xc=0;xc<3;xc++){
            float tot = 0.f;
            #pragma unroll
            for (int dy=0;dy<3;dy++){
                if ((yc==0 && dy==0) || (yc==2 && dy==2)) continue;
                float rs = P[dy*3+1];
                if (xc!=0) rs += P[dy*3+0];
                if (xc!=2) rs += P[dy*3+2];
                tot += rs;
            }
            g_Pb[(s*128+co)*9 + yc*3+xc] = tot;
        }
    }
}

// ---- per-tap MMA ----
__device__ __forceinline__ void conv_tap(uint32_t xb, uint32_t ab, int tap,
                                         int lane, int cob, int pxb,
                                         float acc[4][4][4])
{
    const int lr  = lane & 7;
    const int hsA = lane >> 4;
    const int hsB = (lane >> 3) & 1;
    const int dy = tap/3, dx = tap - dy*3;
    const int dlt = (dy-1)*34 + (dx-1);

    uint32_t rowA[4], rsA[4];
    #pragma unroll
    for (int mi=0;mi<4;mi++){
        int r = cob + mi*16 + lr + ((lane>>3)&1)*8;
        rowA[mi] = (uint32_t)r*256u; rsA[mi] = (uint32_t)(r&7);
    }
    uint32_t rowB[2], rsB[2];
    #pragma unroll
    for (int nn=0;nn<2;nn++){
        int r = 36 + dlt + pxb + nn*16 + lr + (lane>>4)*8;
        rowB[nn] = (uint32_t)r*256u; rsB[nn] = (uint32_t)(r&7);
    }
    #pragma unroll
    for (int k8=0;k8<8;k8++){
        uint32_t a[4][4];
        #pragma unroll
        for (int mi=0;mi<4;mi++){
            uint32_t sgi = (uint32_t)(k8*2 + hsA);
            ldsm4(a[mi][0],a[mi][1],a[mi][2],a[mi][3],
                  ab + rowA[mi] + ((sgi ^ rsA[mi])<<4));
        }
        #pragma unroll
        for (int nn=0;nn<2;nn++){
            uint32_t sgi = (uint32_t)(k8*2 + hsB);
            uint32_t b0,b1,b2,b3;
            ldsm4(b0,b1,b2,b3, xb + rowB[nn] + ((sgi ^ rsB[nn])<<4));
            #pragma unroll
            for (int mi=0;mi<4;mi++){
                mma16816(acc[mi][2*nn],   a[mi][0],a[mi][1],a[mi][2],a[mi][3], b0,b1);
                mma16816(acc[mi][2*nn+1], a[mi][0],a[mi][1],a[mi][2],a[mi][3], b2,b3);
            }
        }
    }
}

// ---- mma.sync fp16 implicit conv: D[128co,128px], 2 CTAs/SM, fused GN sums ----
__global__ __launch_bounds__(256,2)
void mmaconv_k(const __half* __restrict__ wrep,
               const __half* __restrict__ nhwc,
               const float* __restrict__ Pb,
               float* __restrict__ dst,
               float* __restrict__ stats, int nkc, int t0, int t1)
{
    extern __shared__ char dsm[];
    const uint32_t sb = smem_u32(dsm);
    const uint32_t XB = sb;
    const uint32_t AB = sb + AB_OFF;
    const int t = threadIdx.x;
    const int wid = t>>5, lane = t&31;
    const int img = blockIdx.x/10;
    const int p0  = (blockIdx.x%10)*128;
    const int s   = img>>4;
    const int cob = (wid&1)*64;
    const int pxb = (wid>>1)*32;

    float acc[4][4][4];
    #pragma unroll
    for (int mi=0;mi<4;mi++)
    #pragma unroll
    for (int ni=0;ni<4;ni++)
    #pragma unroll
    for (int e=0;e<4;e++) acc[mi][ni][e]=0.f;

    for (int kc=0; kc<nkc; kc++){
        {
            const char* src = (const char*)nhwc
                + ((size_t)GUARD + (size_t)img*RPI + p0 - 36)*512 + kc*256;
            #pragma unroll
            for (int j=0;j<13;j++){
                int i = j*256 + t;
                if (i < 3200){
                    uint32_t r = (uint32_t)(i>>4), sg = (uint32_t)(i&15);
                    cpa16(XB + r*256 + ((sg^(r&7))<<4), src + (size_t)r*512 + sg*16);
                }
            }
            cp_commit();
        }
        for (int tap=t0; tap<t1; tap++){
            const char* asrc = (const char*)(wrep + (size_t)(tap*nkc+kc)*16384);
            #pragma unroll
            for (int j=0;j<8;j++){
                int i = j*256 + t;
                uint32_t r = (uint32_t)(i>>4), sg = (uint32_t)(i&15);
                cpa16(AB + r*256 + ((sg^(r&7))<<4), asrc + (size_t)i*16);
            }
            cp_commit(); cp_wait0(); __syncthreads();
            conv_tap(XB, AB, tap, lane, cob, pxb, acc);
            __syncthreads();
        }
    }

    const int g  = lane>>2;
    const int t2 = (lane&3)*2;
    float sm_=0.f, sq_=0.f;
    #pragma unroll
    for (int mi=0;mi<4;mi++){
        #pragma unroll
        for (int n8=0;n8<4;n8++){
            #pragma unroll
            for (int e=0;e<4;e++){
                int co  = cob + mi*16 + g + ((e>>1)<<3);
                int col = pxb + n8*8 + t2 + (e&1);
                int pp  = p0 + col;
                int q34 = pp/34;
                int yy  = q34 - 1;
                int xx  = pp - q34*34 - 1;
                if ((unsigned)yy < 32u && (unsigned)xx < 32u){
                    float v = acc[mi][n8][e];
                    if (Pb){
                        int yc = (yy==0)?0:((yy==31)?2:1);
                        int xc = (xx==0)?0:((xx==31)?2:1);
                        v += Pb[(s*128+co)*9 + yc*3+xc];
                    }
                    dst[((size_t)img*128+co)*1024 + (yy<<5)+xx] = v;
                    sm_ += v; sq_ += v*v;
                }
            }
        }
    }
    #pragma unroll
    for (int o=16;o;o>>=1){
        sm_ += __shfl_down_sync(0xffffffffu, sm_, o);
        sq_ += __shfl_down_sync(0xffffffffu, sq_, o);
    }
    float* red = (float*)dsm;
    __syncthreads();
    if (lane==0){ red[wid*2] = sm_; red[wid*2+1] = sq_; }
    __syncthreads();
    if (t==0){
        float S=0.f, S2=0.f;
        #pragma unroll
        for (int w=0;w<8;w++){ S += red[w*2]; S2 += red[w*2+1]; }
        atomicAdd(&stats[img*2],   S);
        atomicAdd(&stats[img*2+1], S2);
    }
}

// ---- GN apply from raw sums (o) ----
__global__ void gn_apply_k(float* __restrict__ x, const float* __restrict__ stats,
                           const float* __restrict__ gw, const float* __restrict__ gb,
                           int nimg, int act)
{
    int n4 = nimg*32768;
    for (int i = blockIdx.x*blockDim.x + threadIdx.x; i < n4; i += gridDim.x*blockDim.x){
        int base = i<<2;
        int img = base>>17; int c = (base>>10)&127;
        float sum = stats[2*img], ssq = stats[2*img+1];
        float mu = sum*(1.f/131072.f);
        float rs = rsqrtf(ssq*(1.f/131072.f) - mu*mu + 1e-5f);
        float sc = rs*gw[c];
        float sh = gb[c] - mu*sc;
        float4 v = ((float4*)x)[i];
        v.x = v.x*sc+sh; v.y = v.y*sc+sh; v.z = v.z*sc+sh; v.w = v.w*sc+sh;
        if (act){
            v.x *= sigmf(v.x); v.y *= sigmf(v.y); v.z *= sigmf(v.z); v.w *= sigmf(v.w);
        }
        ((float4*)x)[i] = v;
    }
}

// ---- GN apply + channel mean/max pool fused (k, q) ----
__global__ void gn_apply_pool_k(float* __restrict__ x, const float* __restrict__ stats,
                                const float* __restrict__ gw, const float* __restrict__ gb,
                                float* __restrict__ pool)
{
    __shared__ float sc[128], sh[128];
    int t = threadIdx.x;
    int img = blockIdx.x>>2;
    int p = ((blockIdx.x&3)<<8) + t;
    if (t < 128){
        float sum = stats[2*img], ssq = stats[2*img+1];
        float mu = sum*(1.f/131072.f);
        float rs = rsqrtf(ssq*(1.f/131072.f) - mu*mu + 1e-5f);
        float scv = rs*gw[t];
        sc[t] = scv; sh[t] = gb[t] - mu*scv;
    }
    __syncthreads();
    float* base = x + (size_t)img*CHW + p;
    float s = 0.f, m = -3.402823466e38f;
    #pragma unroll 4
    for (int c=0;c<128;c++){
        float y = base[(size_t)c<<10]*sc[c] + sh[c];
        base[(size_t)c<<10] = y;
        s += y; m = fmaxf(m, y);
    }
    pool[img*2048 + p]        = s*(1.f/128.f);
    pool[img*2048 + 1024 + p] = m;
}

// ---- GN apply att (silu) + newout write fused ----
__global__ void gn_apply_att_k(float* __restrict__ x, const float* __restrict__ stats,
                               const float* __restrict__ gw, const float* __restrict__ gb,
                               const unsigned char* __restrict__ mask,
                               float* __restrict__ out)
{
    int i = blockIdx.x*blockDim.x + threadIdx.x;
    if (i >= BN*32768) return;
    int base = i<<2;
    int img = base>>17; int c = (base>>10)&127;
    float sum = stats[2*img], ssq = stats[2*img+1];
    float mu = sum*(1.f/131072.f);
    float rs = rsqrtf(ssq*(1.f/131072.f) - mu*mu + 1e-5f);
    float sc = rs*gw[c];
    float sh = gb[c] - mu*sc;
    float4 v = ((float4*)x)[i];
    v.x = v.x*sc+sh; v.y = v.y*sc+sh; v.z = v.z*sc+sh; v.w = v.w*sc+sh;
    v.x *= sigmf(v.x); v.y *= sigmf(v.y); v.z *= sigmf(v.z); v.w *= sigmf(v.w);
    ((float4*)x)[i] = v;
    float4 z = mask_at(mask, img) ? v : make_float4(0.f,0.f,0.f,0.f);
    *(float4*)&out[(size_t)2*BN*CHW + base] = z;
}

// ---- 2->1 3x3 conv + sigmoid ----
__global__ void saconv_k(const float* __restrict__ pool, const float* __restrict__ w,
                         const float* __restrict__ b, float* __restrict__ sa, int nimg)
{
    int i = blockIdx.x*blockDim.x + threadIdx.x;
    if (i >= nimg*HWN) return;
    int img = i>>10, p = i&1023, y = p>>5, x = p&31;
    float acc = b[0];
    #pragma unroll
    for (int c2=0;c2<2;c2++)
    #pragma unroll
    for (int dy=-1;dy<=1;dy++)
    #pragma unroll
    for (int dx=-1;dx<=1;dx++){
        int yy=y+dy, xx=x+dx;
        if ((unsigned)yy<32u && (unsigned)xx<32u)
            acc += pool[img*2048 + c2*1024 + (yy<<5)+xx] * w[c2*9 + (dy+1)*3 + (dx+1)];
    }
    sa[i] = sigmf(acc);
}

// ---- fused qfg + t-logit: warp per (s,b,c) ----
__global__ void qfg_tl_k(float* __restrict__ qfg)
{
    int wid  = (blockIdx.x*blockDim.x + threadIdx.x) >> 5;
    int lane = threadIdx.x & 31;
    if (wid >= SN*BN*CH) return;
    int c = wid & 127, b = (wid>>7)&15, s = wid>>11;
    int img = s*16 + b;
    const float* qp = g_q   + ((size_t)b*128 + c)*1024;
    const float* kp = g_k   + ((size_t)img*128 + c)*1024;
    const float* ka = g_ksa + (size_t)img*1024;
    const float* qa = g_qsa + (size_t)b*1024;
    float acc = 0.f, tl = 0.f;
    for (int p=lane; p<1024; p+=32){
        float qv = qp[p], kw = ka[p];
        acc += qv*kw;
        tl  += qv*qa[p]*kp[p]*kw;
    }
    #pragma unroll
    for (int o=16;o;o>>=1){
        acc += __shfl_down_sync(0xffffffffu, acc, o);
        tl  += __shfl_down_sync(0xffffffffu, tl , o);
    }
    if (!lane){
        qfg[wid] = acc*(1.f/1024.f);
        atomicAdd(&g_tl[img], tl);
    }
}

__global__ void sprob_k(const float* __restrict__ qfg)
{
    int img = blockIdx.x;
    __shared__ float fq[128];
    int t = threadIdx.x;
    if (t < 128) fq[t] = qfg[img*128 + t];
    __syncthreads();
    for (int p=t; p<1024; p+=256){
        const float* kp = g_k + (size_t)img*CHW + p;
        float acc = 0.f;
        #pragma unroll 4
        for (int c=0;c<128;c++) acc += fq[c]*kp[(size_t)c<<10];
        g_sprob[img*1024 + p] = sigmf(acc);
    }
}

__global__ void tprob_k()
{
    int b = threadIdx.x;
    if (b >= 16) return;
    const float SCL = rsqrtf(131072.f);
    float m = -3.402823466e38f;
    #pragma unroll
    for (int s=0;s<8;s++) m = fmaxf(m, g_tl[s*16+b]*SCL);
    float e[8]; float sum = 0.f;
    #pragma unroll
    for (int s=0;s<8;s++){ e[s] = __expf(g_tl[s*16+b]*SCL - m); sum += e[s]; }
    float inv = 1.f/sum;
    #pragma unroll
    for (int s=0;s<8;s++) g_tp[s*16+b] = e[s]*inv;
}

// ---- av with fused v-GN, writes fp16 NHWC directly ----
__global__ void av_fill_k(const float* __restrict__ vgw, const float* __restrict__ vgb)
{
    __shared__ float sm[32][129];
    __shared__ float sc[8][128], sh[8][128];
    int t = threadIdx.x;
    int img = blockIdx.x>>5, y = blockIdx.x&31;
    int xg = t&31, cg = t>>5;
    if (t < 128){
        #pragma unroll
        for (int s=0;s<8;s++){
            int i2 = s*16 + img;
            float sum = g_stats[ST_V+2*i2], ssq = g_stats[ST_V+2*i2+1];
            float mu = sum*(1.f/131072.f);
            float rs = rsqrtf(ssq*(1.f/131072.f) - mu*mu + 1e-5f);
            float s_ = rs*vgw[t];
            sc[s][t] = s_; sh[s][t] = vgb[t] - mu*s_;
        }
    }
    __syncthreads();
    int p = y*32 + xg;
    float ws[8];
    #pragma unroll
    for (int s=0;s<8;s++){
        int i2 = s*16 + img;
        ws[s] = g_tp[i2]*g_sprob[i2*1024 + p];
    }
    #pragma unroll
    for (int cc=0; cc<16; cc++){
        int c = cc*8 + cg;
        float acc = 0.f;
        #pragma unroll
        for (int s=0;s<8;s++){
            int i2 = s*16 + img;
            float vv = g_v[((size_t)i2*128 + c)*1024 + p];
            acc += ws[s]*(vv*sc[s][c] + sh[s][c]);
        }
        sm[xg][c] = acc;
    }
    __syncthreads();
    size_t rb = GUARD + (size_t)img*RPI + (size_t)(y+1)*34;
    if (t < 128){
        #pragma unroll
        for (int xs=0; xs<32; xs++)
            g_nhwcS[(rb + xs + 1)*256 + t] = __float2half(sm[xs][t]);
    }
}

// ---- fused SE ----
__global__ void se_k(const float* __restrict__ w1, const float* __restrict__ b1,
                     const float* __restrict__ w2, const float* __restrict__ b2)
{
    __shared__ float mean[128], f1[32];
    int b = blockIdx.x;
    int w = threadIdx.x>>5, lane = threadIdx.x&31;
    for (int c=w; c<128; c+=8){
        const float* p = g_o + ((size_t)b*128 + c)*1024;
        float s = 0.f;
        for (int i=lane; i<1024; i+=32) s += p[i];
        #pragma unroll
        for (int o=16;o;o>>=1) s += __shfl_down_sync(0xffffffffu, s, o);
        if (!lane) mean[c] = s*(1.f/1024.f);
    }
    __syncthreads();
    if (threadIdx.x < 32){
        int j = threadIdx.x;
        float acc = b1[j];
        #pragma unroll 4
        for (int c=0;c<128;c++) acc += mean[c]*w1[j*128+c];
        f1[j] = fmaxf(acc, 0.f);
    }
    __syncthreads();
    if (threadIdx.x < 128){
        int c = threadIdx.x;
        float acc = b2[c];
        #pragma unroll
        for (int j=0;j<32;j++) acc += f1[j]*w2[c*32+j];
        g_se3[b*128+c] = sigmf(acc);
    }
}

__global__ void final_k(float* __restrict__ out)
{
    int i = blockIdx.x*blockDim.x + threadIdx.x;
    if (i >= BN*CHW/4) return;
    int base = i<<2;
    int b = base>>17; int c = (base>>10)&127;
    float g = 1.f + g_se3[b*128+c];
    float4 o4 = *(const float4*)&g_o[base];
    o4.x*=g; o4.y*=g; o4.z*=g; o4.w*=g;
    *(float4*)&out[base] = o4;
    *(float4*)&out[(size_t)BN*CHW + base] = *(const float4*)&g_ht[base];
}

// ---- host launcher ----
extern "C" void kernel_launch(void* const* d_in, const int* in_sizes, int n_in,
                              void* d_out, int out_size)
{
    (void)in_sizes; (void)n_in; (void)out_size;
    const float* inputs  = (const float*)d_in[0];
    const float* hidden  = (const float*)d_in[1];
    const float* outq    = (const float*)d_in[2];
    const unsigned char* mask = (const unsigned char*)d_in[3];
    const float* enc_w   = (const float*)d_in[4];
    const float* enc_gw  = (const float*)d_in[5];
    const float* enc_gb  = (const float*)d_in[6];
    const float* qpre_w  = (const float*)d_in[7];
    const float* qpre_gw = (const float*)d_in[8];
    const float* qpre_gb = (const float*)d_in[9];
    const float* kpre_w  = (const float*)d_in[10];
    const float* kpre_gw = (const float*)d_in[11];
    const float* kpre_gb = (const float*)d_in[12];
    const float* vpre_w  = (const float*)d_in[13];
    const float* vpre_gw = (const float*)d_in[14];
    const float* vpre_gb = (const float*)d_in[15];
    const float* qsa_w   = (const float*)d_in[16];
    const float* qsa_b   = (const float*)d_in[17];
    const float* ksa_w   = (const float*)d_in[18];
    const float* ksa_b   = (const float*)d_in[19];
    const float* vpost_w = (const float*)d_in[20];
    const float* vpost_gw= (const float*)d_in[21];
    const float* vpost_gb= (const float*)d_in[22];
    const float* pos_emb = (const float*)d_in[23];
    const float* outt_w  = (const float*)d_in[24];
    const float* outt_gw = (const float*)d_in[25];
    const float* outt_gb = (const float*)d_in[26];
    const float* se_w1   = (const float*)d_in[27];
    const float* se_b1   = (const float*)d_in[28];
    const float* se_w2   = (const float*)d_in[29];
    const float* se_b2   = (const float*)d_in[30];
    float* out = (float*)d_out;

    float *ht,*q,*k,*v,*att,*o,*stats,*pool,*qsa,*ksa,*peN,*Pb,*qfg;
    __half *wrep, *nhwc, *nhwcS;
    cudaGetSymbolAddress((void**)&ht,   g_ht);
    cudaGetSymbolAddress((void**)&q,    g_q);
    cudaGetSymbolAddress((void**)&k,    g_k);
    cudaGetSymbolAddress((void**)&v,    g_v);
    cudaGetSymbolAddress((void**)&att,  g_att);
    cudaGetSymbolAddress((void**)&o,    g_o);
    cudaGetSymbolAddress((void**)&stats,g_stats);
    cudaGetSymbolAddress((void**)&pool, g_pool);
    cudaGetSymbolAddress((void**)&qsa,  g_qsa);
    cudaGetSymbolAddress((void**)&ksa,  g_ksa);
    cudaGetSymbolAddress((void**)&peN,  g_peN);
    cudaGetSymbolAddress((void**)&Pb,   g_Pb);
    cudaGetSymbolAddress((void**)&qfg,  g_qfg);
    cudaGetSymbolAddress((void**)&wrep, g_wrep);
    cudaGetSymbolAddress((void**)&nhwc, g_nhwc);
    cudaGetSymbolAddress((void**)&nhwcS,g_nhwcS);

    const size_t WR_KPRE  = 0;
    const size_t WR_VPRE  = 294912;
    const size_t WR_QPRE  = 589824;
    const size_t WR_OUTT  = 737280;
    const size_t WR_ENC   = 1032192;
    const size_t WR_VPOST = 1179648;   // accessed as slot 4 via -4*16384 base

    cudaFuncSetAttribute(mmaconv_k, cudaFuncAttributeMaxDynamicSharedMemorySize, DSMEM_TOTAL);

    // persistent streams + events (created once; reused)
    static cudaStream_t s1 = nullptr, s2 = nullptr;
    static cudaEvent_t evA = nullptr, evB = nullptr, evC = nullptr, evD = nullptr;
    if (!s1){
        cudaStreamCreateWithFlags(&s1, cudaStreamNonBlocking);
        cudaStreamCreateWithFlags(&s2, cudaStreamNonBlocking);
        cudaEventCreateWithFlags(&evA, cudaEventDisableTiming);
        cudaEventCreateWithFlags(&evB, cudaEventDisableTiming);
        cudaEventCreateWithFlags(&evC, cudaEventDisableTiming);
        cudaEventCreateWithFlags(&evD, cudaEventDisableTiming);
    }

    zero_stats_k<<<1,768>>>();
    cudaEventRecord(evA, 0);
    cudaStreamWaitEvent(s1, evA, 0);
    cudaStreamWaitEvent(s2, evA, 0);

    // ---- s1: enc -> ht -> qpre -> q pool/saconv ----
    fill_in_k<<<512,256,0,s1>>>(inputs);
    wrep_k<<<576,256,0,s1>>>(enc_w,  wrep + WR_ENC,  64, 1);
    wrep_k<<<576,256,0,s1>>>(qpre_w, wrep + WR_QPRE, 128, 1);
    wrep_k<<<1152,256,0,s1>>>(outt_w, wrep + WR_OUTT, 192, 2);
    wrep1x1_k<<<64,256,0,s1>>>(vpost_w, wrep + WR_VPOST);
    mmaconv_k<<<160,256,DSMEM_TOTAL,s1>>>(wrep + WR_ENC, nhwcS, nullptr, ht,
                                          stats + ST_HT, 1, 0, 9);
    gn_ht_fill_k<<<512,256,0,s1>>>(enc_gw, enc_gb);
    mmaconv_k<<<160,256,DSMEM_TOTAL,s1>>>(wrep + WR_QPRE, nhwcS, nullptr, q,
                                          stats + ST_Q, 1, 0, 9);
    gn_apply_pool_k<<<64,256,0,s1>>>(q, stats + ST_Q, qpre_gw, qpre_gb, pool + 128*2048);
    saconv_k<<<(BN*HWN+255)/256,256,0,s1>>>(pool + 128*2048, qsa_w, qsa_b, qsa, BN);
    cudaEventRecord(evB, s1);

    // ---- main: fill_nhwc, then kpre conv (s2 does vpre conv concurrently) ----
    fill_nhwc_k<<<4096,256>>>(hidden, outq);
    cudaEventRecord(evC, 0);

    // ---- s2: vpre weight prep + conv ----
    wrep_k<<<1152,256,0,s2>>>(vpre_w, wrep + WR_VPRE, 256, 2);
    pe_norm_k<<<8,256,0,s2>>>(pos_emb, peN);
    pbconv_k<<<8,128,0,s2>>>(vpre_w);
    cudaStreamWaitEvent(s2, evC, 0);
    mmaconv_k<<<1280,256,DSMEM_TOTAL,s2>>>(wrep + WR_VPRE, nhwc, Pb, v, stats + ST_V, 2, 0, 9);
    cudaEventRecord(evD, s2);

    // ---- main: kpre conv + k pool ----
    wrep_k<<<1152,256>>>(kpre_w, wrep + WR_KPRE, 256, 2);
    mmaconv_k<<<1280,256,DSMEM_TOTAL>>>(wrep + WR_KPRE, nhwc, nullptr, k, stats + ST_K, 2, 0, 9);
    gn_apply_pool_k<<<512,256>>>(k, stats + ST_K, kpre_gw, kpre_gb, pool);
    saconv_k<<<(SBN*HWN+255)/256,256>>>(pool, ksa_w, ksa_b, ksa, SBN);

    // ---- join q path, run attention ----
    cudaStreamWaitEvent(0, evB, 0);
    qfg_tl_k<<<2048,256>>>(qfg);
    sprob_k<<<SBN,256>>>(qfg);
    tprob_k<<<1,32>>>();
    cudaStreamWaitEvent(0, evD, 0);
    av_fill_k<<<512,256>>>(vpre_gw, vpre_gb);

    // att = silu(gn(mmaconv1x1(av))) + fused newout
    mmaconv_k<<<160,256,DSMEM_TOTAL>>>(wrep + WR_VPOST - 65536, nhwcS, nullptr,
                                       att, stats + ST_ATT, 1, 4, 5);
    gn_apply_att_k<<<2048,256>>>(att, stats + ST_ATT, vpost_gw, vpost_gb, mask, out);

    // o = silu(gn(mmaconv(concat(inputs, att+ht))))
    xcat_fill_k<<<512,256>>>(inputs);
    mmaconv_k<<<160,256,DSMEM_TOTAL>>>(wrep + WR_OUTT, nhwcS, nullptr, o, stats + ST_O, 2, 0, 9);
    gn_apply_k<<<2048,256>>>(o, stats + ST_O, outt_gw, outt_gb, BN, 1);

    se_k<<<BN,256>>>(se_w1, se_b1, se_w2, se_b2);
    final_k<<<2048,256>>>(out);
}

// round 16
// speedup vs baseline: 1.4691x; 1.0664x over previous
#include <cuda_runtime.h>
#include <cuda_fp16.h>
#include <cstdint>

#define BN   16
#define CH   128
#define HWN  1024
#define SN   8
#define SBN  128
#define CHW  131072

#define GUARD   64
#define RPI     1344
#define TOTROWS   (GUARD + 128*RPI + 256)
#define TOTROWS_S (GUARD + 16*RPI + 256)

#define AB_OFF 51200
#define DSMEM_TOTAL 83968

// stats slots (2 floats per img): K=0, V=256, HT=512, Q=544, ATT=576, O=608
#define ST_K   0
#define ST_V   256
#define ST_HT  512
#define ST_Q   544
#define ST_ATT 576
#define ST_O   608

__device__ float g_ht [BN*CHW];
__device__ float g_q  [BN*CHW];
__device__ float g_k  [SBN*CHW];
__device__ float g_v  [SBN*CHW];
__device__ float g_att[BN*CHW];
__device__ float g_o  [BN*CHW];
__device__ float g_stats[640];
__device__ float g_pool[(SBN+BN)*2*HWN];
__device__ float g_qsa[BN*HWN];
__device__ float g_ksa[SBN*HWN];
__device__ float g_sprob[SBN*HWN];
__device__ float g_tl[SN*BN];
__device__ float g_tp[SN*BN];
__device__ float g_peN[SN*2*CH];
__device__ float g_se3[BN*CH];
__device__ float g_Pb[SN*CH*9];
__device__ float g_qfg[SN*BN*CH];
__device__ __half g_nhwc [(size_t)TOTROWS*256];
__device__ __half g_nhwcS[(size_t)TOTROWS_S*256];
// wrep single-split: kpre(294912)|vpre(294912)|qpre(147456)|outt(294912)|enc(147456)|vpost(16384)
__device__ __half g_wrep[1196032];

__device__ __forceinline__ float sigmf(float x){ return 1.f/(1.f + __expf(-x)); }
__device__ __forceinline__ bool mask_at(const unsigned char* m, int b){
    if (m[1] != 0) return m[b] != 0;
    const unsigned int* w = (const unsigned int*)m;
    return w[b] != 0;
}

__device__ __forceinline__ uint32_t smem_u32(const void* p){
    uint32_t a;
    asm("{ .reg .u64 t; cvta.to.shared.u64 t, %1; cvt.u32.u64 %0, t; }" : "=r"(a) : "l"(p));
    return a;
}
__device__ __forceinline__ void mma16816(float* d, uint32_t a0, uint32_t a1, uint32_t a2,
                                         uint32_t a3, uint32_t b0, uint32_t b1){
    asm volatile("mma.sync.aligned.m16n8k16.row.col.f32.f16.f16.f32 "
        "{%0,%1,%2,%3}, {%4,%5,%6,%7}, {%8,%9}, {%0,%1,%2,%3};"
        : "+f"(d[0]),"+f"(d[1]),"+f"(d[2]),"+f"(d[3])
        : "r"(a0),"r"(a1),"r"(a2),"r"(a3),"r"(b0),"r"(b1));
}
__device__ __forceinline__ void ldsm4(uint32_t& r0,uint32_t& r1,uint32_t& r2,uint32_t& r3,
                                      uint32_t addr){
    asm volatile("ldmatrix.sync.aligned.m8n8.x4.shared.b16 {%0,%1,%2,%3}, [%4];"
        : "=r"(r0),"=r"(r1),"=r"(r2),"=r"(r3) : "r"(addr));
}
__device__ __forceinline__ void cpa16(uint32_t d, const void* s){
    asm volatile("cp.async.cg.shared.global [%0], [%1], 16;" :: "r"(d), "l"(s));
}
__device__ __forceinline__ void cp_commit(){ asm volatile("cp.async.commit_group;" ::: "memory"); }
__device__ __forceinline__ void cp_wait0(){ asm volatile("cp.async.wait_group 0;" ::: "memory"); }

// ---- zero stats + t-logits ----
__global__ void zero_stats_k(){
    int t = threadIdx.x;
    if (t < 640) g_stats[t] = 0.f;
    else if (t < 768) g_tl[t-640] = 0.f;
}

__global__ void pe_norm_k(const float* __restrict__ pe, float* __restrict__ peN)
{
    int s = blockIdx.x, t = threadIdx.x;
    float v = pe[s*256 + t];
    float q = v*v;
    #pragma unroll
    for (int o=16;o;o>>=1) q += __shfl_down_sync(0xffffffffu, q, o);
    __shared__ float a[8];
    __shared__ float fac;
    if ((t&31)==0) a[t>>5] = q;
    __syncthreads();
    if (t==0){
        float S=0.f;
        #pragma unroll
        for (int i=0;i<8;i++) S += a[i];
        float n = sqrtf(S);
        fac = fminf(1.f, 1.f/fmaxf(n, 1e-7f));
    }
    __syncthreads();
    peN[s*256 + t] = v*fac;
}

// big buffer fill: kv concat (128 imgs, 256 ch)
__global__ void fill_nhwc_k(const float* __restrict__ hid, const float* __restrict__ oq)
{
    __shared__ float s[32][257];
    int t = threadIdx.x;
    int img = blockIdx.x>>5, y = blockIdx.x&31;
    int xg = t&31, cg = t>>5;
    size_t rb = GUARD + (size_t)img*RPI + (size_t)(y+1)*34;
    #pragma unroll
    for (int cc=0; cc<32; cc++){
        int c = cc*8 + cg;
        const float* src = (c<128) ? hid + ((size_t)img*128 + c)*1024
                                   : oq  + ((size_t)img*128 + (c-128))*1024;
        s[xg][c] = src[y*32 + xg];
    }
    __syncthreads();
    #pragma unroll
    for (int xs=0; xs<32; xs++)
        g_nhwc[(rb + xs + 1)*256 + t] = __float2half(s[xs][t]);
}

// small buffer fill: inputs (ch0-63)
__global__ void fill_in_k(const float* __restrict__ inputs)
{
    __shared__ float s[32][65];
    int t = threadIdx.x;
    int img = blockIdx.x>>5, y = blockIdx.x&31;
    int xg = t&31, cg = t>>5;
    size_t rb = GUARD + (size_t)img*RPI + (size_t)(y+1)*34;
    #pragma unroll
    for (int cc=0; cc<8; cc++){
        int c = cc*8 + cg;
        s[xg][c] = inputs[((size_t)img*64 + c)*1024 + y*32 + xg];
    }
    __syncthreads();
    if (t < 64){
        #pragma unroll
        for (int xs=0; xs<32; xs++)
            g_nhwcS[(rb + xs + 1)*256 + t] = __float2half(s[xs][t]);
    }
}

// gn(ht)+silu in place, fp16 NHWC fill, AND out region 1 write (early, on s1)
__global__ void gn_ht_fill_k(const float* __restrict__ gw, const float* __restrict__ gb,
                             float* __restrict__ out)
{
    __shared__ float sm[32][129];
    __shared__ float sc[128], sh[128];
    int t = threadIdx.x;
    int img = blockIdx.x>>5, y = blockIdx.x&31;
    int xg = t&31, cg = t>>5;
    if (t < 128){
        float sum = g_stats[ST_HT+2*img], ssq = g_stats[ST_HT+2*img+1];
        float mu = sum*(1.f/131072.f);
        float rs = rsqrtf(ssq*(1.f/131072.f) - mu*mu + 1e-5f);
        float s_ = rs*gw[t];
        sc[t] = s_; sh[t] = gb[t] - mu*s_;
    }
    __syncthreads();
    int p = y*32 + xg;
    #pragma unroll
    for (int cc=0; cc<16; cc++){
        int c = cc*8 + cg;
        float v = g_ht[((size_t)img*128 + c)*1024 + p];
        v = v*sc[c] + sh[c];
        v *= sigmf(v);
        g_ht[((size_t)img*128 + c)*1024 + p] = v;
        out[(size_t)BN*CHW + ((size_t)img*128 + c)*1024 + p] = v;
        sm[xg][c] = v;
    }
    __syncthreads();
    size_t rb = GUARD + (size_t)img*RPI + (size_t)(y+1)*34;
    if (t < 128){
        #pragma unroll
        for (int xs=0; xs<32; xs++)
            g_nhwcS[(rb + xs + 1)*256 + t] = __float2half(sm[xs][t]);
    }
}

// fused: gn(att)+silu, masked out-region-2 write, xcat(inputs, att+ht) -> nhwcS
__global__ void gn_att_xcat_k(const float* __restrict__ inputs,
                              const float* __restrict__ stats,
                              const float* __restrict__ gw, const float* __restrict__ gb,
                              const unsigned char* __restrict__ mask,
                              float* __restrict__ out)
{
    __shared__ float s[32][193];
    __shared__ float sc[128], sh[128];
    int t = threadIdx.x;
    int img = blockIdx.x>>5, y = blockIdx.x&31;
    int xg = t&31, cg = t>>5;
    if (t < 128){
        float sum = stats[2*img], ssq = stats[2*img+1];
        float mu = sum*(1.f/131072.f);
        float rs = rsqrtf(ssq*(1.f/131072.f) - mu*mu + 1e-5f);
        float scv = rs*gw[t];
        sc[t] = scv; sh[t] = gb[t] - mu*scv;
    }
    __syncthreads();
    bool mk = mask_at(mask, img);
    int p = y*32 + xg;
    #pragma unroll
    for (int cc=0; cc<8; cc++){
        int c = cc*8 + cg;
        s[xg][c] = inputs[((size_t)img*64 + c)*1024 + p];
    }
    #pragma unroll
    for (int cc=0; cc<16; cc++){
        int c2 = cc*8 + cg;
        float a = g_att[((size_t)img*128 + c2)*1024 + p];
        a = a*sc[c2] + sh[c2];
        a *= sigmf(a);
        out[(size_t)2*BN*CHW + ((size_t)img*128 + c2)*1024 + p] = mk ? a : 0.f;
        s[xg][64 + c2] = a + g_ht[((size_t)img*128 + c2)*1024 + p];
    }
    __syncthreads();
    size_t rb = GUARD + (size_t)img*RPI + (size_t)(y+1)*34;
    if (t < 192){
        #pragma unroll
        for (int xs=0; xs<32; xs++)
            g_nhwcS[(rb + xs + 1)*256 + t] = __float2half(s[xs][t]);
    }
}

// ---- weight repack: [tap*nkc+kc][co][128k] fp16 single split; zero-pad cin ----
__global__ void wrep_k(const float* __restrict__ w, __half* __restrict__ dst,
                       int cin, int nkc)
{
    int n = nkc*147456;
    int i = blockIdx.x*blockDim.x + threadIdx.x;
    if (i >= n) return;
    int kl = i & 127;
    int r = i >> 7;
    int co = r & 127; r >>= 7;
    int kc = r % nkc;
    int tap = r / nkc;
    int cin_idx = kc*128 + kl;
    float val = (cin_idx < cin) ? w[((size_t)co*cin + cin_idx)*9 + tap] : 0.f;
    dst[((tap*nkc+kc)*128 + co)*128 + kl] = __float2half(val);
}

__global__ void wrep1x1_k(const float* __restrict__ w, __half* __restrict__ dst)
{
    int i = blockIdx.x*blockDim.x + threadIdx.x;
    if (i < 16384) dst[i] = __float2half(w[i]);
}

// ---- pe correction with border masks ----
__global__ void pbconv_k(const float* __restrict__ w)
{
    int s = blockIdx.x, co = threadIdx.x;
    float P[9];
    #pragma unroll
    for (int tap=0;tap<9;tap++){
        float acc = 0.f;
        for (int c=0;c<256;c++)
            acc += g_peN[s*256 + c] * w[((size_t)co*256 + c)*9 + tap];
        P[tap] = acc;
    }
    #pragma unroll
    for (int yc=0;yc<3;yc++){
        #pragma unroll
        for (int xc=0;xc<3;xc++){
            float tot = 0.f;
            #pragma unroll
            for (int dy=0;dy<3;dy++){
                if ((yc==0 && dy==0) || (yc==2 && dy==2)) continue;
                float rs = P[dy*3+1];
                if (xc!=0) rs += P[dy*3+0];
                if (xc!=2) rs += P[dy*3+2];
                tot += rs;
            }
            g_Pb[(s*128+co)*9 + yc*3+xc] = tot;
        }
    }
}

// ---- per-tap MMA ----
__device__ __forceinline__ void conv_tap(uint32_t xb, uint32_t ab, int tap,
                                         int lane, int cob, int pxb,
                                         float acc[4][4][4])
{
    const int lr  = lane & 7;
    const int hsA = lane >> 4;
    const int hsB = (lane >> 3) & 1;
    const int dy = tap/3, dx = tap - dy*3;
    const int dlt = (dy-1)*34 + (dx-1);

    uint32_t rowA[4], rsA[4];
    #pragma unroll
    for (int mi=0;mi<4;mi++){
        int r = cob + mi*16 + lr + ((lane>>3)&1)*8;
        rowA[mi] = (uint32_t)r*256u; rsA[mi] = (uint32_t)(r&7);
    }
    uint32_t rowB[2], rsB[2];
    #pragma unroll
    for (int nn=0;nn<2;nn++){
        int r = 36 + dlt + pxb + nn*16 + lr + (lane>>4)*8;
        rowB[nn] = (uint32_t)r*256u; rsB[nn] = (uint32_t)(r&7);
    }
    #pragma unroll
    for (int k8=0;k8<8;k8++){
        uint32_t a[4][4];
        #pragma unroll
        for (int mi=0;mi<4;mi++){
            uint32_t sgi = (uint32_t)(k8*2 + hsA);
            ldsm4(a[mi][0],a[mi][1],a[mi][2],a[mi][3],
                  ab + rowA[mi] + ((sgi ^ rsA[mi])<<4));
        }
        #pragma unroll
        for (int nn=0;nn<2;nn++){
            uint32_t sgi = (uint32_t)(k8*2 + hsB);
            uint32_t b0,b1,b2,b3;
            ldsm4(b0,b1,b2,b3, xb + rowB[nn] + ((sgi ^ rsB[nn])<<4));
            #pragma unroll
            for (int mi=0;mi<4;mi++){
                mma16816(acc[mi][2*nn],   a[mi][0],a[mi][1],a[mi][2],a[mi][3], b0,b1);
                mma16816(acc[mi][2*nn+1], a[mi][0],a[mi][1],a[mi][2],a[mi][3], b2,b3);
            }
        }
    }
}

// ---- mma.sync fp16 implicit conv: D[128co,128px], 2 CTAs/SM, fused GN sums ----
__global__ __launch_bounds__(256,2)
void mmaconv_k(const __half* __restrict__ wrep,
               const __half* __restrict__ nhwc,
               const float* __restrict__ Pb,
               float* __restrict__ dst,
               float* __restrict__ stats, int nkc, int t0, int t1)
{
    extern __shared__ char dsm[];
    const uint32_t sb = smem_u32(dsm);
    const uint32_t XB = sb;
    const uint32_t AB = sb + AB_OFF;
    const int t = threadIdx.x;
    const int wid = t>>5, lane = t&31;
    const int img = blockIdx.x/10;
    const int p0  = (blockIdx.x%10)*128;
    const int s   = img>>4;
    const int cob = (wid&1)*64;
    const int pxb = (wid>>1)*32;

    float acc[4][4][4];
    #pragma unroll
    for (int mi=0;mi<4;mi++)
    #pragma unroll
    for (int ni=0;ni<4;ni++)
    #pragma unroll
    for (int e=0;e<4;e++) acc[mi][ni][e]=0.f;

    for (int kc=0; kc<nkc; kc++){
        {
            const char* src = (const char*)nhwc
                + ((size_t)GUARD + (size_t)img*RPI + p0 - 36)*512 + kc*256;
            #pragma unroll
            for (int j=0;j<13;j++){
                int i = j*256 + t;
                if (i < 3200){
                    uint32_t r = (uint32_t)(i>>4), sg = (uint32_t)(i&15);
                    cpa16(XB + r*256 + ((sg^(r&7))<<4), src + (size_t)r*512 + sg*16);
                }
            }
            cp_commit();
        }
        for (int tap=t0; tap<t1; tap++){
            const char* asrc = (const char*)(wrep + (size_t)(tap*nkc+kc)*16384);
            #pragma unroll
            for (int j=0;j<8;j++){
                int i = j*256 + t;
                uint32_t r = (uint32_t)(i>>4), sg = (uint32_t)(i&15);
                cpa16(AB + r*256 + ((sg^(r&7))<<4), asrc + (size_t)i*16);
            }
            cp_commit(); cp_wait0(); __syncthreads();
            conv_tap(XB, AB, tap, lane, cob, pxb, acc);
            __syncthreads();
        }
    }

    const int g  = lane>>2;
    const int t2 = (lane&3)*2;
    float sm_=0.f, sq_=0.f;
    #pragma unroll
    for (int mi=0;mi<4;mi++){
        #pragma unroll
        for (int n8=0;n8<4;n8++){
            #pragma unroll
            for (int e=0;e<4;e++){
                int co  = cob + mi*16 + g + ((e>>1)<<3);
                int col = pxb + n8*8 + t2 + (e&1);
                int pp  = p0 + col;
                int q34 = pp/34;
                int yy  = q34 - 1;
                int xx  = pp - q34*34 - 1;
                if ((unsigned)yy < 32u && (unsigned)xx < 32u){
                    float v = acc[mi][n8][e];
                    if (Pb){
                        int yc = (yy==0)?0:((yy==31)?2:1);
                        int xc = (xx==0)?0:((xx==31)?2:1);
                        v += Pb[(s*128+co)*9 + yc*3+xc];
                    }
                    dst[((size_t)img*128+co)*1024 + (yy<<5)+xx] = v;
                    sm_ += v; sq_ += v*v;
                }
            }
        }
    }
    #pragma unroll
    for (int o=16;o;o>>=1){
        sm_ += __shfl_down_sync(0xffffffffu, sm_, o);
        sq_ += __shfl_down_sync(0xffffffffu, sq_, o);
    }
    float* red = (float*)dsm;
    __syncthreads();
    if (lane==0){ red[wid*2] = sm_; red[wid*2+1] = sq_; }
    __syncthreads();
    if (t==0){
        float S=0.f, S2=0.f;
        #pragma unroll
        for (int w=0;w<8;w++){ S += red[w*2]; S2 += red[w*2+1]; }
        atomicAdd(&stats[img*2],   S);
        atomicAdd(&stats[img*2+1], S2);
    }
}

// ---- GN apply from raw sums (o) ----
__global__ void gn_apply_k(float* __restrict__ x, const float* __restrict__ stats,
                           const float* __restrict__ gw, const float* __restrict__ gb,
                           int nimg, int act)
{
    int n4 = nimg*32768;
    for (int i = blockIdx.x*blockDim.x + threadIdx.x; i < n4; i += gridDim.x*blockDim.x){
        int base = i<<2;
        int img = base>>17; int c = (base>>10)&127;
        float sum = stats[2*img], ssq = stats[2*img+1];
        float mu = sum*(1.f/131072.f);
        float rs = rsqrtf(ssq*(1.f/131072.f) - mu*mu + 1e-5f);
        float sc = rs*gw[c];
        float sh = gb[c] - mu*sc;
        float4 v = ((float4*)x)[i];
        v.x = v.x*sc+sh; v.y = v.y*sc+sh; v.z = v.z*sc+sh; v.w = v.w*sc+sh;
        if (act){
            v.x *= sigmf(v.x); v.y *= sigmf(v.y); v.z *= sigmf(v.z); v.w *= sigmf(v.w);
        }
        ((float4*)x)[i] = v;
    }
}

// ---- GN apply + channel mean/max pool fused (k, q) ----
__global__ void gn_apply_pool_k(float* __restrict__ x, const float* __restrict__ stats,
                                const float* __restrict__ gw, const float* __restrict__ gb,
                                float* __restrict__ pool)
{
    __shared__ float sc[128], sh[128];
    int t = threadIdx.x;
    int img = blockIdx.x>>2;
    int p = ((blockIdx.x&3)<<8) + t;
    if (t < 128){
        float sum = stats[2*img], ssq = stats[2*img+1];
        float mu = sum*(1.f/131072.f);
        float rs = rsqrtf(ssq*(1.f/131072.f) - mu*mu + 1e-5f);
        float scv = rs*gw[t];
        sc[t] = scv; sh[t] = gb[t] - mu*scv;
    }
    __syncthreads();
    float* base = x + (size_t)img*CHW + p;
    float s = 0.f, m = -3.402823466e38f;
    #pragma unroll 4
    for (int c=0;c<128;c++){
        float y = base[(size_t)c<<10]*sc[c] + sh[c];
        base[(size_t)c<<10] = y;
        s += y; m = fmaxf(m, y);
    }
    pool[img*2048 + p]        = s*(1.f/128.f);
    pool[img*2048 + 1024 + p] = m;
}

// ---- 2->1 3x3 conv + sigmoid ----
__global__ void saconv_k(const float* __restrict__ pool, const float* __restrict__ w,
                         const float* __restrict__ b, float* __restrict__ sa, int nimg)
{
    int i = blockIdx.x*blockDim.x + threadIdx.x;
    if (i >= nimg*HWN) return;
    int img = i>>10, p = i&1023, y = p>>5, x = p&31;
    float acc = b[0];
    #pragma unroll
    for (int c2=0;c2<2;c2++)
    #pragma unroll
    for (int dy=-1;dy<=1;dy++)
    #pragma unroll
    for (int dx=-1;dx<=1;dx++){
        int yy=y+dy, xx=x+dx;
        if ((unsigned)yy<32u && (unsigned)xx<32u)
            acc += pool[img*2048 + c2*1024 + (yy<<5)+xx] * w[c2*9 + (dy+1)*3 + (dx+1)];
    }
    sa[i] = sigmf(acc);
}

// ---- fused qfg + t-logit: warp per (s,b,c) ----
__global__ void qfg_tl_k(float* __restrict__ qfg)
{
    int wid  = (blockIdx.x*blockDim.x + threadIdx.x) >> 5;
    int lane = threadIdx.x & 31;
    if (wid >= SN*BN*CH) return;
    int c = wid & 127, b = (wid>>7)&15, s = wid>>11;
    int img = s*16 + b;
    const float* qp = g_q   + ((size_t)b*128 + c)*1024;
    const float* kp = g_k   + ((size_t)img*128 + c)*1024;
    const float* ka = g_ksa + (size_t)img*1024;
    const float* qa = g_qsa + (size_t)b*1024;
    float acc = 0.f, tl = 0.f;
    for (int p=lane; p<1024; p+=32){
        float qv = qp[p], kw = ka[p];
        acc += qv*kw;
        tl  += qv*qa[p]*kp[p]*kw;
    }
    #pragma unroll
    for (int o=16;o;o>>=1){
        acc += __shfl_down_sync(0xffffffffu, acc, o);
        tl  += __shfl_down_sync(0xffffffffu, tl , o);
    }
    if (!lane){
        qfg[wid] = acc*(1.f/1024.f);
        atomicAdd(&g_tl[img], tl);
    }
}

// 1024 blocks x 128 threads: img x 8 pixel chunks
__global__ void sprob_k(const float* __restrict__ qfg)
{
    __shared__ float fq[128];
    int img = blockIdx.x>>3;
    int p0  = (blockIdx.x&7)<<7;
    int t = threadIdx.x;
    fq[t] = qfg[img*128 + t];
    __syncthreads();
    int p = p0 + t;
    const float* kp = g_k + (size_t)img*CHW + p;
    float acc = 0.f;
    #pragma unroll 4
    for (int c=0;c<128;c++) acc += fq[c]*kp[(size_t)c<<10];
    g_sprob[img*1024 + p] = sigmf(acc);
}

__global__ void tprob_k()
{
    int b = threadIdx.x;
    if (b >= 16) return;
    const float SCL = rsqrtf(131072.f);
    float m = -3.402823466e38f;
    #pragma unroll
    for (int s=0;s<8;s++) m = fmaxf(m, g_tl[s*16+b]*SCL);
    float e[8]; float sum = 0.f;
    #pragma unroll
    for (int s=0;s<8;s++){ e[s] = __expf(g_tl[s*16+b]*SCL - m); sum += e[s]; }
    float inv = 1.f/sum;
    #pragma unroll
    for (int s=0;s<8;s++) g_tp[s*16+b] = e[s]*inv;
}

// ---- av with fused v-GN, writes fp16 NHWC directly ----
__global__ void av_fill_k(const float* __restrict__ vgw, const float* __restrict__ vgb)
{
    __shared__ float sm[32][129];
    __shared__ float sc[8][128], sh[8][128];
    int t = threadIdx.x;
    int img = blockIdx.x>>5, y = blockIdx.x&31;
    int xg = t&31, cg = t>>5;
    if (t < 128){
        #pragma unroll
        for (int s=0;s<8;s++){
            int i2 = s*16 + img;
            float sum = g_stats[ST_V+2*i2], ssq = g_stats[ST_V+2*i2+1];
            float mu = sum*(1.f/131072.f);
            float rs = rsqrtf(ssq*(1.f/131072.f) - mu*mu + 1e-5f);
            float s_ = rs*vgw[t];
            sc[s][t] = s_; sh[s][t] = vgb[t] - mu*s_;
        }
    }
    __syncthreads();
    int p = y*32 + xg;
    float ws[8];
    #pragma unroll
    for (int s=0;s<8;s++){
        int i2 = s*16 + img;
        ws[s] = g_tp[i2]*g_sprob[i2*1024 + p];
    }
    #pragma unroll
    for (int cc=0; cc<16; cc++){
        int c = cc*8 + cg;
        float acc = 0.f;
        #pragma unroll
        for (int s=0;s<8;s++){
            int i2 = s*16 + img;
            float vv = g_v[((size_t)i2*128 + c)*1024 + p];
            acc += ws[s]*(vv*sc[s][c] + sh[s][c]);
        }
        sm[xg][c] = acc;
    }
    __syncthreads();
    size_t rb = GUARD + (size_t)img*RPI + (size_t)(y+1)*34;
    if (t < 128){
        #pragma unroll
        for (int xs=0; xs<32; xs++)
            g_nhwcS[(rb + xs + 1)*256 + t] = __float2half(sm[xs][t]);
    }
}

// ---- fused SE ----
__global__ void se_k(const float* __restrict__ w1, const float* __restrict__ b1,
                     const float* __restrict__ w2, const float* __restrict__ b2)
{
    __shared__ float mean[128], f1[32];
    int b = blockIdx.x;
    int w = threadIdx.x>>5, lane = threadIdx.x&31;
    for (int c=w; c<128; c+=8){
        const float* p = g_o + ((size_t)b*128 + c)*1024;
        float s = 0.f;
        for (int i=lane; i<1024; i+=32) s += p[i];
        #pragma unroll
        for (int o=16;o;o>>=1) s += __shfl_down_sync(0xffffffffu, s, o);
        if (!lane) mean[c] = s*(1.f/1024.f);
    }
    __syncthreads();
    if (threadIdx.x < 32){
        int j = threadIdx.x;
        float acc = b1[j];
        #pragma unroll 4
        for (int c=0;c<128;c++) acc += mean[c]*w1[j*128+c];
        f1[j] = fmaxf(acc, 0.f);
    }
    __syncthreads();
    if (threadIdx.x < 128){
        int c = threadIdx.x;
        float acc = b2[c];
        #pragma unroll
        for (int j=0;j<32;j++) acc += f1[j]*w2[c*32+j];
        g_se3[b*128+c] = sigmf(acc);
    }
}

// out region 0 only (region 1 written by gn_ht_fill, region 2 by gn_att_xcat)
__global__ void final_k(float* __restrict__ out)
{
    int i = blockIdx.x*blockDim.x + threadIdx.x;
    if (i >= BN*CHW/4) return;
    int base = i<<2;
    int b = base>>17; int c = (base>>10)&127;
    float g = 1.f + g_se3[b*128+c];
    float4 o4 = *(const float4*)&g_o[base];
    o4.x*=g; o4.y*=g; o4.z*=g; o4.w*=g;
    *(float4*)&out[base] = o4;
}

// ---- host launcher ----
extern "C" void kernel_launch(void* const* d_in, const int* in_sizes, int n_in,
                              void* d_out, int out_size)
{
    (void)in_sizes; (void)n_in; (void)out_size;
    const float* inputs  = (const float*)d_in[0];
    const float* hidden  = (const float*)d_in[1];
    const float* outq    = (const float*)d_in[2];
    const unsigned char* mask = (const unsigned char*)d_in[3];
    const float* enc_w   = (const float*)d_in[4];
    const float* enc_gw  = (const float*)d_in[5];
    const float* enc_gb  = (const float*)d_in[6];
    const float* qpre_w  = (const float*)d_in[7];
    const float* qpre_gw = (const float*)d_in[8];
    const float* qpre_gb = (const float*)d_in[9];
    const float* kpre_w  = (const float*)d_in[10];
    const float* kpre_gw = (const float*)d_in[11];
    const float* kpre_gb = (const float*)d_in[12];
    const float* vpre_w  = (const float*)d_in[13];
    const float* vpre_gw = (const float*)d_in[14];
    const float* vpre_gb = (const float*)d_in[15];
    const float* qsa_w   = (const float*)d_in[16];
    const float* qsa_b   = (const float*)d_in[17];
    const float* ksa_w   = (const float*)d_in[18];
    const float* ksa_b   = (const float*)d_in[19];
    const float* vpost_w = (const float*)d_in[20];
    const float* vpost_gw= (const float*)d_in[21];
    const float* vpost_gb= (const float*)d_in[22];
    const float* pos_emb = (const float*)d_in[23];
    const float* outt_w  = (const float*)d_in[24];
    const float* outt_gw = (const float*)d_in[25];
    const float* outt_gb = (const float*)d_in[26];
    const float* se_w1   = (const float*)d_in[27];
    const float* se_b1   = (const float*)d_in[28];
    const float* se_w2   = (const float*)d_in[29];
    const float* se_b2   = (const float*)d_in[30];
    float* out = (float*)d_out;

    float *ht,*q,*k,*v,*att,*o,*stats,*pool,*qsa,*ksa,*peN,*Pb,*qfg;
    __half *wrep, *nhwc, *nhwcS;
    cudaGetSymbolAddress((void**)&ht,   g_ht);
    cudaGetSymbolAddress((void**)&q,    g_q);
    cudaGetSymbolAddress((void**)&k,    g_k);
    cudaGetSymbolAddress((void**)&v,    g_v);
    cudaGetSymbolAddress((void**)&att,  g_att);
    cudaGetSymbolAddress((void**)&o,    g_o);
    cudaGetSymbolAddress((void**)&stats,g_stats);
    cudaGetSymbolAddress((void**)&pool, g_pool);
    cudaGetSymbolAddress((void**)&qsa,  g_qsa);
    cudaGetSymbolAddress((void**)&ksa,  g_ksa);
    cudaGetSymbolAddress((void**)&peN,  g_peN);
    cudaGetSymbolAddress((void**)&Pb,   g_Pb);
    cudaGetSymbolAddress((void**)&qfg,  g_qfg);
    cudaGetSymbolAddress((void**)&wrep, g_wrep);
    cudaGetSymbolAddress((void**)&nhwc, g_nhwc);
    cudaGetSymbolAddress((void**)&nhwcS,g_nhwcS);

    const size_t WR_KPRE  = 0;
    const size_t WR_VPRE  = 294912;
    const size_t WR_QPRE  = 589824;
    const size_t WR_OUTT  = 737280;
    const size_t WR_ENC   = 1032192;
    const size_t WR_VPOST = 1179648;   // accessed as slot 4 via -4*16384 base

    cudaFuncSetAttribute(mmaconv_k, cudaFuncAttributeMaxDynamicSharedMemorySize, DSMEM_TOTAL);

    // persistent streams + events (created once; reused)
    static cudaStream_t s1 = nullptr, s2 = nullptr;
    static cudaEvent_t evA = nullptr, evB = nullptr, evC = nullptr, evD = nullptr;
    if (!s1){
        cudaStreamCreateWithFlags(&s1, cudaStreamNonBlocking);
        cudaStreamCreateWithFlags(&s2, cudaStreamNonBlocking);
        cudaEventCreateWithFlags(&evA, cudaEventDisableTiming);
        cudaEventCreateWithFlags(&evB, cudaEventDisableTiming);
        cudaEventCreateWithFlags(&evC, cudaEventDisableTiming);
        cudaEventCreateWithFlags(&evD, cudaEventDisableTiming);
    }

    zero_stats_k<<<1,768>>>();
    cudaEventRecord(evA, 0);
    cudaStreamWaitEvent(s1, evA, 0);
    cudaStreamWaitEvent(s2, evA, 0);

    // ---- s1: enc -> ht -> qpre -> q pool/saconv (ht also written to out region 1) ----
    fill_in_k<<<512,256,0,s1>>>(inputs);
    wrep_k<<<576,256,0,s1>>>(enc_w,  wrep + WR_ENC,  64, 1);
    wrep_k<<<576,256,0,s1>>>(qpre_w, wrep + WR_QPRE, 128, 1);
    wrep_k<<<1152,256,0,s1>>>(outt_w, wrep + WR_OUTT, 192, 2);
    wrep1x1_k<<<64,256,0,s1>>>(vpost_w, wrep + WR_VPOST);
    mmaconv_k<<<160,256,DSMEM_TOTAL,s1>>>(wrep + WR_ENC, nhwcS, nullptr, ht,
                                          stats + ST_HT, 1, 0, 9);
    gn_ht_fill_k<<<512,256,0,s1>>>(enc_gw, enc_gb, out);
    mmaconv_k<<<160,256,DSMEM_TOTAL,s1>>>(wrep + WR_QPRE, nhwcS, nullptr, q,
                                          stats + ST_Q, 1, 0, 9);
    gn_apply_pool_k<<<64,256,0,s1>>>(q, stats + ST_Q, qpre_gw, qpre_gb, pool + 128*2048);
    saconv_k<<<(BN*HWN+255)/256,256,0,s1>>>(pool + 128*2048, qsa_w, qsa_b, qsa, BN);
    cudaEventRecord(evB, s1);

    // ---- main: fill_nhwc, then kpre conv (s2 does vpre conv concurrently) ----
    fill_nhwc_k<<<4096,256>>>(hidden, outq);
    cudaEventRecord(evC, 0);

    // ---- s2: vpre weight prep + conv ----
    wrep_k<<<1152,256,0,s2>>>(vpre_w, wrep + WR_VPRE, 256, 2);
    pe_norm_k<<<8,256,0,s2>>>(pos_emb, peN);
    pbconv_k<<<8,128,0,s2>>>(vpre_w);
    cudaStreamWaitEvent(s2, evC, 0);
    mmaconv_k<<<1280,256,DSMEM_TOTAL,s2>>>(wrep + WR_VPRE, nhwc, Pb, v, stats + ST_V, 2, 0, 9);
    cudaEventRecord(evD, s2);

    // ---- main: kpre conv + k pool ----
    wrep_k<<<1152,256>>>(kpre_w, wrep + WR_KPRE, 256, 2);
    mmaconv_k<<<1280,256,DSMEM_TOTAL>>>(wrep + WR_KPRE, nhwc, nullptr, k, stats + ST_K, 2, 0, 9);
    gn_apply_pool_k<<<512,256>>>(k, stats + ST_K, kpre_gw, kpre_gb, pool);
    saconv_k<<<(SBN*HWN+255)/256,256>>>(pool, ksa_w, ksa_b, ksa, SBN);

    // ---- join q path, run attention ----
    cudaStreamWaitEvent(0, evB, 0);
    qfg_tl_k<<<2048,256>>>(qfg);
    sprob_k<<<1024,128>>>(qfg);
    tprob_k<<<1,32>>>();
    cudaStreamWaitEvent(0, evD, 0);
    av_fill_k<<<512,256>>>(vpre_gw, vpre_gb);

    // att = gn(mmaconv1x1(av)) raw -> fused gn+silu+newout+xcat
    mmaconv_k<<<160,256,DSMEM_TOTAL>>>(wrep + WR_VPOST - 65536, nhwcS, nullptr,
                                       att, stats + ST_ATT, 1, 4, 5);
    gn_att_xcat_k<<<512,256>>>(inputs, stats + ST_ATT, vpost_gw, vpost_gb, mask, out);

    // o = silu(gn(mmaconv(xcat)))
    mmaconv_k<<<160,256,DSMEM_TOTAL>>>(wrep + WR_OUTT, nhwcS, nullptr, o, stats + ST_O, 2, 0, 9);
    gn_apply_k<<<2048,256>>>(o, stats + ST_O, outt_gw, outt_gb, BN, 1);

    se_k<<<BN,256>>>(se_w1, se_b1, se_w2, se_b2);
    final_k<<<2048,256>>>(out);
}